// round 11
// baseline (speedup 1.0000x reference)
#include <cuda_runtime.h>
#include <cuda_bf16.h>
#include <math.h>

// Problem shapes (fixed by the dataset)
#define NB 4
#define NT 1024
#define ND 512
#define NH 8
#define NDH 64
#define NR 2047          // 2*T - 1
#define NM 4096          // B*T
#define NROWS (NB * NH * NT)   // 32768 score rows
#define NKT 8                  // k-tiles of 128 per row
#define NW 256                 // words per row (512 floats / 2)

#define PW 36            // padded word-row length (32 data words + 4)
#define GSW 196          // Gs row stride (191 cols + pad)

// ---------------- device scratch (no allocations allowed) ----------------
__device__ unsigned gQh[NM * NW];
__device__ unsigned gQl[NM * NW];
__device__ unsigned gKh[NM * NW];
__device__ unsigned gKl[NM * NW];
__device__ unsigned gEh[NR * NW];
__device__ unsigned gEl[NR * NW];
__device__ float gV[NM * ND];
__device__ float gPE[NR * ND];
__device__ float gS[33554432];        // B*H*T*T, holds exp(s - m_tile)
__device__ float gO[NM * ND];
__device__ float gUK[NB * NH * NT];
__device__ float gVE[NH * NR];
__device__ float gPartM[NROWS * NKT];
__device__ float gPartL[NROWS * NKT];
__device__ float gScale[NROWS * NKT];

// ---------------- bf16 split helpers ----------------
__device__ __forceinline__ void cvt_pair2(float a, float b, unsigned& hi, unsigned& lo) {
    unsigned ha = __bfloat16_as_ushort(__float2bfloat16(a));
    unsigned hb = __bfloat16_as_ushort(__float2bfloat16(b));
    float ra = a - __bfloat162float(__ushort_as_bfloat16((unsigned short)ha));
    float rb = b - __bfloat162float(__ushort_as_bfloat16((unsigned short)hb));
    unsigned la = __bfloat16_as_ushort(__float2bfloat16(ra));
    unsigned lb = __bfloat16_as_ushort(__float2bfloat16(rb));
    hi = (hb << 16) | ha;
    lo = (lb << 16) | la;
}
__device__ __forceinline__ float2 unpack2(unsigned w) {
    return make_float2(__bfloat162float(__ushort_as_bfloat16((unsigned short)(w & 0xffff))),
                       __bfloat162float(__ushort_as_bfloat16((unsigned short)(w >> 16))));
}
__device__ __forceinline__ void mma16(float (&c)[4], unsigned a0, unsigned a1,
                                      unsigned a2, unsigned a3, unsigned b0, unsigned b1) {
    asm volatile(
        "mma.sync.aligned.m16n8k16.row.col.f32.bf16.bf16.f32 "
        "{%0,%1,%2,%3},{%4,%5,%6,%7},{%8,%9},{%0,%1,%2,%3};"
        : "+f"(c[0]), "+f"(c[1]), "+f"(c[2]), "+f"(c[3])
        : "r"(a0), "r"(a1), "r"(a2), "r"(a3), "r"(b0), "r"(b1));
}
__device__ __forceinline__ unsigned smaddr(const void* p) {
    return (unsigned)__cvta_generic_to_shared(p);
}
__device__ __forceinline__ void ldsm4(unsigned& r0, unsigned& r1, unsigned& r2,
                                      unsigned& r3, unsigned a) {
    asm volatile("ldmatrix.sync.aligned.m8n8.x4.shared.b16 {%0,%1,%2,%3}, [%4];"
                 : "=r"(r0), "=r"(r1), "=r"(r2), "=r"(r3) : "r"(a));
}
// A-fragment lane offset (bytes): row = lane&15, +16B for lanes 16-31
#define AOFF(lane) (((((lane) & 15) * PW + ((lane) >> 4) * 4)) << 2)
// B-fragment lane offset (two n-blocks of 8)
#define BOFF(lane) (((((((lane) >> 4) << 3) + ((lane) & 7)) * PW + (((lane) >> 3) & 1) * 4)) << 2)

// ---------------- positional encoding ----------------
__global__ void pe_kernel() {
    int idx = blockIdx.x * 256 + threadIdx.x;
    if (idx >= NR * 256) return;
    int r = idx >> 8;
    int m = idx & 255;
    float inv = exp2f(-(float)m * (13.287712379549449f / 256.0f));
    float ang = (float)(1023 - r) * inv;
    gPE[r * ND + 2 * m]     = (float)sin((double)ang);
    gPE[r * ND + 2 * m + 1] = (float)cos((double)ang);
}

// ---------------- GEMM body -------------------------------------------
struct ProjArgs {
    const float* A[4];
    const float* W[4];
    const float* bias[4];
    unsigned*    Ch[4];
    unsigned*    Cl[4];
    float*       Cf[4];
    int          M[4];
    int          split[4];
};

__device__ __forceinline__ void proj_body(const float* __restrict__ A,
                                          const float* __restrict__ W,
                                          const float* __restrict__ bias,
                                          unsigned* Ch, unsigned* Cl, float* Cf,
                                          int M, int do_split,
                                          int bx, int by, unsigned* sm) {
    unsigned* Ah = sm;                    // 128*PW
    unsigned* Al = Ah + 128 * PW;
    unsigned* Wh = Al + 128 * PW;         // 64*PW, stored [n][kword]
    unsigned* Wl = Wh + 64 * PW;
    int tid = threadIdx.x;
    int warp = tid >> 5, lane = tid & 31;
    int wm = warp >> 1, wn = warp & 1;
    int g = lane >> 2, t = lane & 3;
    int bm = by * 128, bn = bx * 64;
    float acc[2][4][4] = {};
    unsigned uAh = smaddr(Ah), uAl = smaddr(Al), uWh = smaddr(Wh), uWl = smaddr(Wl);
    unsigned aoff = AOFF(lane), boff = BOFF(lane);

    for (int k0 = 0; k0 < 512; k0 += 64) {
        #pragma unroll
        for (int i = 0; i < 8; i++) {
            int idx = tid + i * 256;
            int row = idx >> 4, c4 = (idx & 15) << 2;
            int grow = bm + row;
            float4 av = (grow < M) ? *(const float4*)&A[(size_t)grow * 512 + k0 + c4]
                                   : make_float4(0.f, 0.f, 0.f, 0.f);
            int w = c4 >> 1;
            unsigned h0, l0, h1, l1;
            cvt_pair2(av.x, av.y, h0, l0);
            cvt_pair2(av.z, av.w, h1, l1);
            *(uint2*)&Ah[row * PW + w] = make_uint2(h0, h1);
            *(uint2*)&Al[row * PW + w] = make_uint2(l0, l1);
        }
        #pragma unroll
        for (int i = 0; i < 4; i++) {
            int idx = tid + i * 256;
            int row = idx >> 4, c4 = (idx & 15) << 2;
            float4 wv = *(const float4*)&W[(size_t)(bn + row) * 512 + k0 + c4];
            int w = c4 >> 1;
            unsigned h0, l0, h1, l1;
            cvt_pair2(wv.x, wv.y, h0, l0);
            cvt_pair2(wv.z, wv.w, h1, l1);
            *(uint2*)&Wh[row * PW + w] = make_uint2(h0, h1);
            *(uint2*)&Wl[row * PW + w] = make_uint2(l0, l1);
        }
        __syncthreads();
        #pragma unroll
        for (int kw = 0; kw < 32; kw += 8) {
            unsigned ah[2][4], al[2][4];
            #pragma unroll
            for (int mt = 0; mt < 2; mt++) {
                unsigned base = (((wm * 32 + mt * 16) * PW + kw) << 2) + aoff;
                ldsm4(ah[mt][0], ah[mt][1], ah[mt][2], ah[mt][3], uAh + base);
                ldsm4(al[mt][0], al[mt][1], al[mt][2], al[mt][3], uAl + base);
            }
            #pragma unroll
            for (int pair = 0; pair < 2; pair++) {
                unsigned base = (((wn * 32 + pair * 16) * PW + kw) << 2) + boff;
                unsigned bh[4], bl[4];
                ldsm4(bh[0], bh[1], bh[2], bh[3], uWh + base);
                ldsm4(bl[0], bl[1], bl[2], bl[3], uWl + base);
                #pragma unroll
                for (int half = 0; half < 2; half++) {
                    int nt = pair * 2 + half;
                    unsigned bh0 = bh[half * 2], bh1 = bh[half * 2 + 1];
                    unsigned bl0 = bl[half * 2], bl1 = bl[half * 2 + 1];
                    #pragma unroll
                    for (int mt = 0; mt < 2; mt++) {
                        mma16(acc[mt][nt], ah[mt][0], ah[mt][1], ah[mt][2], ah[mt][3], bh0, bh1);
                        mma16(acc[mt][nt], ah[mt][0], ah[mt][1], ah[mt][2], ah[mt][3], bl0, bl1);
                        mma16(acc[mt][nt], al[mt][0], al[mt][1], al[mt][2], al[mt][3], bh0, bh1);
                    }
                }
            }
        }
        __syncthreads();
    }
    #pragma unroll
    for (int mt = 0; mt < 2; mt++) {
        #pragma unroll
        for (int nt = 0; nt < 4; nt++) {
            int row = bm + wm * 32 + mt * 16 + g;
            int col = bn + wn * 32 + nt * 8 + t * 2;
            float f0 = acc[mt][nt][0] + bias[col];
            float f1 = acc[mt][nt][1] + bias[col + 1];
            float f2 = acc[mt][nt][2] + bias[col];
            float f3 = acc[mt][nt][3] + bias[col + 1];
            if (do_split) {
                unsigned h0, l0;
                if (row < M) {
                    cvt_pair2(f0, f1, h0, l0);
                    Ch[(size_t)row * NW + (col >> 1)] = h0;
                    Cl[(size_t)row * NW + (col >> 1)] = l0;
                }
                if (row + 8 < M) {
                    cvt_pair2(f2, f3, h0, l0);
                    Ch[(size_t)(row + 8) * NW + (col >> 1)] = h0;
                    Cl[(size_t)(row + 8) * NW + (col >> 1)] = l0;
                }
            } else {
                if (row < M) {
                    Cf[(size_t)row * 512 + col]     = f0;
                    Cf[(size_t)row * 512 + col + 1] = f1;
                }
                if (row + 8 < M) {
                    Cf[(size_t)(row + 8) * 512 + col]     = f2;
                    Cf[(size_t)(row + 8) * 512 + col + 1] = f3;
                }
            }
        }
    }
}

__global__ void proj_all(ProjArgs a) {
    extern __shared__ unsigned sm[];
    int bid = blockIdx.x;
    int z, bx, by;
    if (bid < 768) { z = bid >> 8; int r = bid & 255; by = r >> 3; bx = r & 7; }
    else           { z = 3;        int r = bid - 768; by = r >> 3; bx = r & 7; }
    proj_body(a.A[z], a.W[z], a.bias[z], a.Ch[z], a.Cl[z], a.Cf[z], a.M[z], a.split[z],
              bx, by, sm);
}

__global__ void proj_out(const float* __restrict__ A, const float* __restrict__ W,
                         const float* __restrict__ bias, float* __restrict__ C, int M) {
    extern __shared__ unsigned sm[];
    proj_body(A, W, bias, 0, 0, C, M, 0, blockIdx.x, blockIdx.y, sm);
}

// ---------------- gUK + gVE fused (from split arrays) ------------------
__global__ void ukve_kernel(const float* __restrict__ u, const float* __restrict__ v) {
    int gid = blockIdx.x * 256 + threadIdx.x;
    int w = gid >> 5, lane = gid & 31;
    if (w < NB * NH * NT) {
        int t = w & (NT - 1);
        int bh = w >> 10;
        int h = bh & 7, b = bh >> 3;
        size_t base = (size_t)(b * NT + t) * NW + h * 32 + lane;
        float2 kh = unpack2(gKh[base]);
        float2 kl = unpack2(gKl[base]);
        const float* up = u + h * NDH;
        float s = (kh.x + kl.x) * up[2 * lane] + (kh.y + kl.y) * up[2 * lane + 1];
        #pragma unroll
        for (int o = 16; o; o >>= 1) s += __shfl_down_sync(0xffffffffu, s, o);
        if (lane == 0) gUK[bh * NT + t] = s;
    } else {
        int w2 = w - NB * NH * NT;
        if (w2 >= NH * NR) return;
        int h = w2 / NR;
        int r = w2 - h * NR;
        size_t base = (size_t)r * NW + h * 32 + lane;
        float2 eh = unpack2(gEh[base]);
        float2 el = unpack2(gEl[base]);
        const float* vp = v + h * NDH;
        float s = (eh.x + el.x) * vp[2 * lane] + (eh.y + el.y) * vp[2 * lane + 1];
        #pragma unroll
        for (int o = 16; o; o >>= 1) s += __shfl_down_sync(0xffffffffu, s, o);
        if (lane == 0) gVE[h * NR + r] = s;
    }
}

// ---------------- scores: 64q x 128k, single-pass fused GEMMs -------------
// Dedicated buffers for K, E0, E1 so Q fragments are loaded once per kw step
// and feed all three GEMMs. 8 warps (2m x 4n), 32x32 warp tiles.
__global__ void scores_tc() {
    extern __shared__ unsigned sm[];
    unsigned* Qh  = sm;                     // 64*PW
    unsigned* Ql  = Qh  + 64 * PW;
    unsigned* Kh  = Ql  + 64 * PW;          // 128*PW
    unsigned* Kl  = Kh  + 128 * PW;
    unsigned* E0h = Kl  + 128 * PW;         // 128*PW
    unsigned* E0l = E0h + 128 * PW;
    unsigned* E1h = E0l + 128 * PW;         // 64*PW
    unsigned* E1l = E1h + 64 * PW;
    float* Gs   = (float*)(E1l + 64 * PW);  // 64*GSW
    float* redM = Gs + 64 * GSW;            // [4][64]
    float* redL = redM + 256;               // [4][64]
    int tid = threadIdx.x;
    int bh = blockIdx.z, h = bh & 7, b = bh >> 3;
    int q0 = blockIdx.y * 64, k0 = blockIdx.x * 128;
    int warp = tid >> 5, lane = tid & 31;
    int wm = warp >> 2, wn = warp & 3;
    int g = lane >> 2, t = lane & 3;
    unsigned uQh = smaddr(Qh), uQl = smaddr(Ql);
    unsigned uKh = smaddr(Kh), uKl = smaddr(Kl);
    unsigned uE0h = smaddr(E0h), uE0l = smaddr(E0l);
    unsigned uE1h = smaddr(E1h), uE1l = smaddr(E1l);
    unsigned aoff = AOFF(lane), boff = BOFF(lane);
    int rbase = 960 + k0 - q0;   // >= 0 always; r = rbase + c, c = k + 63 - q
    const uint4 zero4 = make_uint4(0, 0, 0, 0);

    // ---- load ALL tiles: Q(64), K(128), E0(128), E1(64) ----
    #pragma unroll
    for (int i = 0; i < 2; i++) {
        int idx = tid + i * 256;
        int row = idx >> 3, w4 = (idx & 7) << 2;
        size_t gbase = (size_t)(b * NT + q0 + row) * NW + h * 32 + w4;
        *(uint4*)&Qh[row * PW + w4] = *(const uint4*)&gQh[gbase];
        *(uint4*)&Ql[row * PW + w4] = *(const uint4*)&gQl[gbase];
    }
    #pragma unroll
    for (int i = 0; i < 4; i++) {
        int idx = tid + i * 256;
        int row = idx >> 3, w4 = (idx & 7) << 2;
        size_t gbase = (size_t)(b * NT + k0 + row) * NW + h * 32 + w4;
        *(uint4*)&Kh[row * PW + w4] = *(const uint4*)&gKh[gbase];
        *(uint4*)&Kl[row * PW + w4] = *(const uint4*)&gKl[gbase];
    }
    #pragma unroll
    for (int i = 0; i < 4; i++) {
        int idx = tid + i * 256;
        int row = idx >> 3, w4 = (idx & 7) << 2;
        int r = rbase + row;
        size_t gbase = (size_t)r * NW + h * 32 + w4;
        *(uint4*)&E0h[row * PW + w4] = (r < NR) ? *(const uint4*)&gEh[gbase] : zero4;
        *(uint4*)&E0l[row * PW + w4] = (r < NR) ? *(const uint4*)&gEl[gbase] : zero4;
    }
    #pragma unroll
    for (int i = 0; i < 2; i++) {
        int idx = tid + i * 256;
        int row = idx >> 3, w4 = (idx & 7) << 2;
        int r = rbase + 128 + row;
        size_t gbase = (size_t)r * NW + h * 32 + w4;
        *(uint4*)&E1h[row * PW + w4] = (r < NR) ? *(const uint4*)&gEh[gbase] : zero4;
        *(uint4*)&E1l[row * PW + w4] = (r < NR) ? *(const uint4*)&gEl[gbase] : zero4;
    }
    __syncthreads();

    // ---- fused GEMM loop: Q fragments loaded once per kw step ----
    float accK[2][4][4] = {};
    float accE[2][4][4] = {};
    float accF[2][2][4] = {};
    #pragma unroll
    for (int kw = 0; kw < 32; kw += 8) {
        unsigned ah[2][4], al[2][4];
        #pragma unroll
        for (int mt = 0; mt < 2; mt++) {
            unsigned base = (((wm * 32 + mt * 16) * PW + kw) << 2) + aoff;
            ldsm4(ah[mt][0], ah[mt][1], ah[mt][2], ah[mt][3], uQh + base);
            ldsm4(al[mt][0], al[mt][1], al[mt][2], al[mt][3], uQl + base);
        }
        // QK
        #pragma unroll
        for (int pair = 0; pair < 2; pair++) {
            unsigned base = (((wn * 32 + pair * 16) * PW + kw) << 2) + boff;
            unsigned bhv[4], blv[4];
            ldsm4(bhv[0], bhv[1], bhv[2], bhv[3], uKh + base);
            ldsm4(blv[0], blv[1], blv[2], blv[3], uKl + base);
            #pragma unroll
            for (int half = 0; half < 2; half++) {
                int nt = pair * 2 + half;
                #pragma unroll
                for (int mt = 0; mt < 2; mt++) {
                    mma16(accK[mt][nt], ah[mt][0], ah[mt][1], ah[mt][2], ah[mt][3],
                          bhv[half*2], bhv[half*2+1]);
                    mma16(accK[mt][nt], ah[mt][0], ah[mt][1], ah[mt][2], ah[mt][3],
                          blv[half*2], blv[half*2+1]);
                    mma16(accK[mt][nt], al[mt][0], al[mt][1], al[mt][2], al[mt][3],
                          bhv[half*2], bhv[half*2+1]);
                }
            }
        }
        // E0
        #pragma unroll
        for (int pair = 0; pair < 2; pair++) {
            unsigned base = (((wn * 32 + pair * 16) * PW + kw) << 2) + boff;
            unsigned bhv[4], blv[4];
            ldsm4(bhv[0], bhv[1], bhv[2], bhv[3], uE0h + base);
            ldsm4(blv[0], blv[1], blv[2], blv[3], uE0l + base);
            #pragma unroll
            for (int half = 0; half < 2; half++) {
                int nt = pair * 2 + half;
                #pragma unroll
                for (int mt = 0; mt < 2; mt++) {
                    mma16(accE[mt][nt], ah[mt][0], ah[mt][1], ah[mt][2], ah[mt][3],
                          bhv[half*2], bhv[half*2+1]);
                    mma16(accE[mt][nt], ah[mt][0], ah[mt][1], ah[mt][2], ah[mt][3],
                          blv[half*2], blv[half*2+1]);
                    mma16(accE[mt][nt], al[mt][0], al[mt][1], al[mt][2], al[mt][3],
                          bhv[half*2], bhv[half*2+1]);
                }
            }
        }
        // E1 (warp n-width 16)
        {
            unsigned base = (((wn * 16) * PW + kw) << 2) + boff;
            unsigned bhv[4], blv[4];
            ldsm4(bhv[0], bhv[1], bhv[2], bhv[3], uE1h + base);
            ldsm4(blv[0], blv[1], blv[2], blv[3], uE1l + base);
            #pragma unroll
            for (int half = 0; half < 2; half++) {
                #pragma unroll
                for (int mt = 0; mt < 2; mt++) {
                    mma16(accF[mt][half], ah[mt][0], ah[mt][1], ah[mt][2], ah[mt][3],
                          bhv[half*2], bhv[half*2+1]);
                    mma16(accF[mt][half], ah[mt][0], ah[mt][1], ah[mt][2], ah[mt][3],
                          blv[half*2], blv[half*2+1]);
                    mma16(accF[mt][half], al[mt][0], al[mt][1], al[mt][2], al[mt][3],
                          bhv[half*2], bhv[half*2+1]);
                }
            }
        }
    }

    // ---- write E results to Gs ----
    #pragma unroll
    for (int mt = 0; mt < 2; mt++)
        #pragma unroll
        for (int nt = 0; nt < 4; nt++) {
            int row = wm * 32 + mt * 16 + g;
            int col = wn * 32 + nt * 8 + t * 2;
            Gs[row * GSW + col]           = accE[mt][nt][0];
            Gs[row * GSW + col + 1]       = accE[mt][nt][1];
            Gs[(row + 8) * GSW + col]     = accE[mt][nt][2];
            Gs[(row + 8) * GSW + col + 1] = accE[mt][nt][3];
        }
    #pragma unroll
    for (int mt = 0; mt < 2; mt++)
        #pragma unroll
        for (int nt = 0; nt < 2; nt++) {
            int row = wm * 32 + mt * 16 + g;
            int col = 128 + wn * 16 + nt * 8 + t * 2;
            Gs[row * GSW + col]           = accF[mt][nt][0];
            Gs[row * GSW + col + 1]       = accF[mt][nt][1];
            Gs[(row + 8) * GSW + col]     = accF[mt][nt][2];
            Gs[(row + 8) * GSW + col + 1] = accF[mt][nt][3];
        }
    __syncthreads();

    // ---- gather full raw scores ----
    #pragma unroll
    for (int mt = 0; mt < 2; mt++)
        #pragma unroll
        for (int nt = 0; nt < 4; nt++) {
            int kb = wn * 32 + nt * 8 + t * 2;
            #pragma unroll
            for (int r4 = 0; r4 < 4; r4++) {
                int q = wm * 32 + mt * 16 + g + ((r4 >= 2) ? 8 : 0);
                int k = kb + (r4 & 1);
                int c = k + 63 - q;
                accK[mt][nt][r4] = (accK[mt][nt][r4] + Gs[q * GSW + c]
                                    + gUK[bh * NT + k0 + k] + gVE[h * NR + rbase + c]) * 0.125f;
            }
        }

    // ---- per-tile row stats ----
    float mrow[2][2];
    #pragma unroll
    for (int mt = 0; mt < 2; mt++) {
        mrow[mt][0] = -1e30f; mrow[mt][1] = -1e30f;
        #pragma unroll
        for (int nt = 0; nt < 4; nt++) {
            mrow[mt][0] = fmaxf(mrow[mt][0], fmaxf(accK[mt][nt][0], accK[mt][nt][1]));
            mrow[mt][1] = fmaxf(mrow[mt][1], fmaxf(accK[mt][nt][2], accK[mt][nt][3]));
        }
        #pragma unroll
        for (int hf = 0; hf < 2; hf++) {
            mrow[mt][hf] = fmaxf(mrow[mt][hf], __shfl_xor_sync(0xffffffffu, mrow[mt][hf], 1));
            mrow[mt][hf] = fmaxf(mrow[mt][hf], __shfl_xor_sync(0xffffffffu, mrow[mt][hf], 2));
        }
    }
    if (t == 0) {
        #pragma unroll
        for (int mt = 0; mt < 2; mt++)
            #pragma unroll
            for (int hf = 0; hf < 2; hf++)
                redM[wn * 64 + wm * 32 + mt * 16 + g + hf * 8] = mrow[mt][hf];
    }
    __syncthreads();
    #pragma unroll
    for (int mt = 0; mt < 2; mt++)
        #pragma unroll
        for (int hf = 0; hf < 2; hf++) {
            int row = wm * 32 + mt * 16 + g + hf * 8;
            mrow[mt][hf] = fmaxf(fmaxf(redM[row], redM[64 + row]),
                                 fmaxf(redM[128 + row], redM[192 + row]));
        }

    float srow[2][2] = {};
    #pragma unroll
    for (int mt = 0; mt < 2; mt++)
        #pragma unroll
        for (int nt = 0; nt < 4; nt++) {
            accK[mt][nt][0] = __expf(accK[mt][nt][0] - mrow[mt][0]);
            accK[mt][nt][1] = __expf(accK[mt][nt][1] - mrow[mt][0]);
            accK[mt][nt][2] = __expf(accK[mt][nt][2] - mrow[mt][1]);
            accK[mt][nt][3] = __expf(accK[mt][nt][3] - mrow[mt][1]);
            srow[mt][0] += accK[mt][nt][0] + accK[mt][nt][1];
            srow[mt][1] += accK[mt][nt][2] + accK[mt][nt][3];
        }
    #pragma unroll
    for (int mt = 0; mt < 2; mt++)
        #pragma unroll
        for (int hf = 0; hf < 2; hf++) {
            srow[mt][hf] += __shfl_xor_sync(0xffffffffu, srow[mt][hf], 1);
            srow[mt][hf] += __shfl_xor_sync(0xffffffffu, srow[mt][hf], 2);
        }
    if (t == 0) {
        #pragma unroll
        for (int mt = 0; mt < 2; mt++)
            #pragma unroll
            for (int hf = 0; hf < 2; hf++)
                redL[wn * 64 + wm * 32 + mt * 16 + g + hf * 8] = srow[mt][hf];
    }
    __syncthreads();
    if (wn == 0 && t == 0) {
        #pragma unroll
        for (int mt = 0; mt < 2; mt++)
            #pragma unroll
            for (int hf = 0; hf < 2; hf++) {
                int row = wm * 32 + mt * 16 + g + hf * 8;
                size_t ri = (size_t)(bh * NT + q0 + row) * NKT + blockIdx.x;
                gPartM[ri] = mrow[mt][hf];
                gPartL[ri] = redL[row] + redL[64 + row] + redL[128 + row] + redL[192 + row];
            }
    }

    // ---- store exp values ----
    #pragma unroll
    for (int mt = 0; mt < 2; mt++)
        #pragma unroll
        for (int nt = 0; nt < 4; nt++) {
            int kb = wn * 32 + nt * 8 + t * 2;
            #pragma unroll
            for (int r4 = 0; r4 < 4; r4++) {
                int q = wm * 32 + mt * 16 + g + ((r4 >= 2) ? 8 : 0);
                int k = kb + (r4 & 1);
                gS[(size_t)(bh * NT + q0 + q) * NT + k0 + k] = accK[mt][nt][r4];
            }
        }
}

// ---------------- combine per-tile stats -> per-(row,tile) scales --------
__global__ void reduce_kernel() {
    int row = blockIdx.x * 256 + threadIdx.x;
    if (row >= NROWS) return;
    size_t base = (size_t)row * NKT;
    float m = -1e30f;
    float pm[NKT], pl[NKT];
    #pragma unroll
    for (int i = 0; i < NKT; i++) {
        pm[i] = gPartM[base + i];
        pl[i] = gPartL[base + i];
        m = fmaxf(m, pm[i]);
    }
    float l = 0.f;
    #pragma unroll
    for (int i = 0; i < NKT; i++) l += __expf(pm[i] - m) * pl[i];
    float inv = 1.f / l;
    #pragma unroll
    for (int i = 0; i < NKT; i++) gScale[base + i] = __expf(pm[i] - m) * inv;
}

// ---------------- O = P @ V: 128 thr, 4 warps, 32x32 warp tiles ----------
__global__ void pv_tc() {
    extern __shared__ unsigned sm[];
    unsigned* Ph  = sm;                   // 64*PW
    unsigned* Pl  = Ph + 64 * PW;
    unsigned* Vth = Pl + 64 * PW;         // 64*PW, [d][posword]
    unsigned* Vtl = Vth + 64 * PW;
    int tid = threadIdx.x;
    int warp = tid >> 5, lane = tid & 31;
    int wm = warp >> 1, wn = warp & 1;
    int g = lane >> 2, t = lane & 3;
    int bh = blockIdx.y, b = bh >> 3, h = bh & 7;
    int q0 = blockIdx.x * 64;
    float acc[2][4][4] = {};
    unsigned uPh = smaddr(Ph), uPl = smaddr(Pl), uVh = smaddr(Vth), uVl = smaddr(Vtl);
    unsigned aoff = AOFF(lane), boff = BOFF(lane);

    for (int kk0 = 0; kk0 < NT; kk0 += 64) {
        int kt8 = kk0 >> 7;
        #pragma unroll
        for (int i = 0; i < 8; i++) {
            int idx = tid + i * 128;
            int row = idx >> 4, c4 = (idx & 15) << 2;
            float sc = gScale[(size_t)(bh * NT + q0 + row) * NKT + kt8];
            float4 pv = *(const float4*)&gS[(size_t)(bh * NT + q0 + row) * NT + kk0 + c4];
            int w = c4 >> 1;
            unsigned h0, l0, h1, l1;
            cvt_pair2(pv.x * sc, pv.y * sc, h0, l0);
            cvt_pair2(pv.z * sc, pv.w * sc, h1, l1);
            *(uint2*)&Ph[row * PW + w] = make_uint2(h0, h1);
            *(uint2*)&Pl[row * PW + w] = make_uint2(l0, l1);
        }
        #pragma unroll
        for (int i = 0; i < 4; i++) {
            int u = tid + i * 128;
            int p = u >> 4, dg = (u & 15) << 2;
            const float* v0 = &gV[(size_t)(b * NT + kk0 + 2 * p) * ND + h * NDH + dg];
            const float* v1 = v0 + ND;
            float4 a = *(const float4*)v0;
            float4 c = *(const float4*)v1;
            unsigned hv, lv;
            cvt_pair2(a.x, c.x, hv, lv); Vth[(dg + 0) * PW + p] = hv; Vtl[(dg + 0) * PW + p] = lv;
            cvt_pair2(a.y, c.y, hv, lv); Vth[(dg + 1) * PW + p] = hv; Vtl[(dg + 1) * PW + p] = lv;
            cvt_pair2(a.z, c.z, hv, lv); Vth[(dg + 2) * PW + p] = hv; Vtl[(dg + 2) * PW + p] = lv;
            cvt_pair2(a.w, c.w, hv, lv); Vth[(dg + 3) * PW + p] = hv; Vtl[(dg + 3) * PW + p] = lv;
        }
        __syncthreads();
        #pragma unroll
        for (int kw = 0; kw < 32; kw += 8) {
            unsigned ah[2][4], al[2][4];
            #pragma unroll
            for (int mt = 0; mt < 2; mt++) {
                unsigned base = (((wm * 32 + mt * 16) * PW + kw) << 2) + aoff;
                ldsm4(ah[mt][0], ah[mt][1], ah[mt][2], ah[mt][3], uPh + base);
                ldsm4(al[mt][0], al[mt][1], al[mt][2], al[mt][3], uPl + base);
            }
            #pragma unroll
            for (int pair = 0; pair < 2; pair++) {
                unsigned base = (((wn * 32 + pair * 16) * PW + kw) << 2) + boff;
                unsigned bhv[4], blv[4];
                ldsm4(bhv[0], bhv[1], bhv[2], bhv[3], uVh + base);
                ldsm4(blv[0], blv[1], blv[2], blv[3], uVl + base);
                #pragma unroll
                for (int half = 0; half < 2; half++) {
                    int nt = pair * 2 + half;
                    #pragma unroll
                    for (int mt = 0; mt < 2; mt++) {
                        mma16(acc[mt][nt], ah[mt][0], ah[mt][1], ah[mt][2], ah[mt][3],
                              bhv[half*2], bhv[half*2+1]);
                        mma16(acc[mt][nt], ah[mt][0], ah[mt][1], ah[mt][2], ah[mt][3],
                              blv[half*2], blv[half*2+1]);
                        mma16(acc[mt][nt], al[mt][0], al[mt][1], al[mt][2], al[mt][3],
                              bhv[half*2], bhv[half*2+1]);
                    }
                }
            }
        }
        __syncthreads();
    }
    #pragma unroll
    for (int mt = 0; mt < 2; mt++)
        #pragma unroll
        for (int nt = 0; nt < 4; nt++) {
            int row = q0 + wm * 32 + mt * 16 + g;
            int col = wn * 32 + nt * 8 + t * 2;
            gO[(size_t)(b * NT + row) * ND + h * NDH + col]         = acc[mt][nt][0];
            gO[(size_t)(b * NT + row) * ND + h * NDH + col + 1]     = acc[mt][nt][1];
            gO[(size_t)(b * NT + row + 8) * ND + h * NDH + col]     = acc[mt][nt][2];
            gO[(size_t)(b * NT + row + 8) * ND + h * NDH + col + 1] = acc[mt][nt][3];
        }
}

// -------------------------------------------------------------------------
extern "C" void kernel_launch(void* const* d_in, const int* in_sizes, int n_in,
                              void* d_out, int out_size) {
    const float* query = (const float*)d_in[0];
    const float* key_  = (const float*)d_in[1];
    const float* value = (const float*)d_in[2];
    const float* Wq = (const float*)d_in[3];
    const float* bq = (const float*)d_in[4];
    const float* Wk = (const float*)d_in[5];
    const float* bk = (const float*)d_in[6];
    const float* Wv = (const float*)d_in[7];
    const float* bv = (const float*)d_in[8];
    const float* Wp = (const float*)d_in[9];
    const float* bp = (const float*)d_in[10];
    const float* Wo = (const float*)d_in[11];
    const float* bo = (const float*)d_in[12];
    const float* ub = (const float*)d_in[13];
    const float* vb = (const float*)d_in[14];
    float* out = (float*)d_out;

    unsigned *pQh, *pQl, *pKh, *pKl, *pEh, *pEl;
    float *pV, *pPE, *pO;
    cudaGetSymbolAddress((void**)&pQh, gQh);
    cudaGetSymbolAddress((void**)&pQl, gQl);
    cudaGetSymbolAddress((void**)&pKh, gKh);
    cudaGetSymbolAddress((void**)&pKl, gKl);
    cudaGetSymbolAddress((void**)&pEh, gEh);
    cudaGetSymbolAddress((void**)&pEl, gEl);
    cudaGetSymbolAddress((void**)&pV, gV);
    cudaGetSymbolAddress((void**)&pPE, gPE);
    cudaGetSymbolAddress((void**)&pO, gO);

    const int PROJ_SMEM   = (2 * 128 * PW + 2 * 64 * PW) * 4;                     // 55296
    const int SCORES_SMEM = (2 * PW * (64 + 128 + 128 + 64) + 64 * GSW + 512) * 4; // 162816
    const int PV_SMEM     = (4 * 64 * PW) * 4;                                    // 36864
    cudaFuncSetAttribute(proj_all,  cudaFuncAttributeMaxDynamicSharedMemorySize, PROJ_SMEM);
    cudaFuncSetAttribute(proj_out,  cudaFuncAttributeMaxDynamicSharedMemorySize, PROJ_SMEM);
    cudaFuncSetAttribute(scores_tc, cudaFuncAttributeMaxDynamicSharedMemorySize, SCORES_SMEM);
    cudaFuncSetAttribute(pv_tc,     cudaFuncAttributeMaxDynamicSharedMemorySize, PV_SMEM);

    ProjArgs pa;
    pa.A[0] = query; pa.W[0] = Wq; pa.bias[0] = bq; pa.M[0] = NM;
    pa.Ch[0] = pQh;  pa.Cl[0] = pQl; pa.Cf[0] = 0;  pa.split[0] = 1;
    pa.A[1] = key_;  pa.W[1] = Wk; pa.bias[1] = bk; pa.M[1] = NM;
    pa.Ch[1] = pKh;  pa.Cl[1] = pKl; pa.Cf[1] = 0;  pa.split[1] = 1;
    pa.A[2] = value; pa.W[2] = Wv; pa.bias[2] = bv; pa.M[2] = NM;
    pa.Ch[2] = 0;    pa.Cl[2] = 0;   pa.Cf[2] = pV; pa.split[2] = 0;
    pa.A[3] = pPE;   pa.W[3] = Wp; pa.bias[3] = bp; pa.M[3] = NR;
    pa.Ch[3] = pEh;  pa.Cl[3] = pEl; pa.Cf[3] = 0;  pa.split[3] = 1;

    pe_kernel<<<NR, 256>>>();
    proj_all<<<896, 256, PROJ_SMEM>>>(pa);
    ukve_kernel<<<6143, 256>>>(ub, vb);
    scores_tc<<<dim3(8, 16, 32), 256, SCORES_SMEM>>>();
    reduce_kernel<<<128, 256>>>();
    pv_tc<<<dim3(16, 32), 128, PV_SMEM>>>();
    proj_out<<<dim3(8, 32), 256, PROJ_SMEM>>>(pO, Wo, bo, out, NM);
}

// round 12
// speedup vs baseline: 1.0889x; 1.0889x over previous
#include <cuda_runtime.h>
#include <cuda_bf16.h>
#include <math.h>

// Problem shapes (fixed by the dataset)
#define NB 4
#define NT 1024
#define ND 512
#define NH 8
#define NDH 64
#define NR 2047          // 2*T - 1
#define NM 4096          // B*T
#define NROWS (NB * NH * NT)   // 32768 score rows
#define NKT 8                  // k-tiles of 128 per row
#define NW 256                 // words per row (512 floats / 2)

#define PW 36            // padded word-row length (32 data words + 4)
#define GSW 196          // Gs row stride (191 cols + pad)

// ---------------- device scratch (no allocations allowed) ----------------
__device__ unsigned gQh[NM * NW];
__device__ unsigned gQl[NM * NW];
__device__ unsigned gKh[NM * NW];
__device__ unsigned gKl[NM * NW];
__device__ unsigned gEh[NR * NW];
__device__ unsigned gEl[NR * NW];
__device__ float gV[NM * ND];
__device__ float gPE[NR * ND];
__device__ float gS[33554432];        // B*H*T*T, holds exp(s - m_tile)
__device__ float gO[NM * ND];
__device__ float gUK[NB * NH * NT];
__device__ float gVE[NH * NR];
__device__ float gPartM[NROWS * NKT];
__device__ float gPartL[NROWS * NKT];
__device__ float gScale[NROWS * NKT];

// ---------------- bf16 split helpers ----------------
__device__ __forceinline__ void cvt_pair2(float a, float b, unsigned& hi, unsigned& lo) {
    unsigned ha = __bfloat16_as_ushort(__float2bfloat16(a));
    unsigned hb = __bfloat16_as_ushort(__float2bfloat16(b));
    float ra = a - __bfloat162float(__ushort_as_bfloat16((unsigned short)ha));
    float rb = b - __bfloat162float(__ushort_as_bfloat16((unsigned short)hb));
    unsigned la = __bfloat16_as_ushort(__float2bfloat16(ra));
    unsigned lb = __bfloat16_as_ushort(__float2bfloat16(rb));
    hi = (hb << 16) | ha;
    lo = (lb << 16) | la;
}
__device__ __forceinline__ float2 unpack2(unsigned w) {
    return make_float2(__bfloat162float(__ushort_as_bfloat16((unsigned short)(w & 0xffff))),
                       __bfloat162float(__ushort_as_bfloat16((unsigned short)(w >> 16))));
}
__device__ __forceinline__ void mma16(float (&c)[4], unsigned a0, unsigned a1,
                                      unsigned a2, unsigned a3, unsigned b0, unsigned b1) {
    asm volatile(
        "mma.sync.aligned.m16n8k16.row.col.f32.bf16.bf16.f32 "
        "{%0,%1,%2,%3},{%4,%5,%6,%7},{%8,%9},{%0,%1,%2,%3};"
        : "+f"(c[0]), "+f"(c[1]), "+f"(c[2]), "+f"(c[3])
        : "r"(a0), "r"(a1), "r"(a2), "r"(a3), "r"(b0), "r"(b1));
}
__device__ __forceinline__ unsigned smaddr(const void* p) {
    return (unsigned)__cvta_generic_to_shared(p);
}
__device__ __forceinline__ void ldsm4(unsigned& r0, unsigned& r1, unsigned& r2,
                                      unsigned& r3, unsigned a) {
    asm volatile("ldmatrix.sync.aligned.m8n8.x4.shared.b16 {%0,%1,%2,%3}, [%4];"
                 : "=r"(r0), "=r"(r1), "=r"(r2), "=r"(r3) : "r"(a));
}
// A-fragment lane offset (bytes): row = lane&15, +16B for lanes 16-31
#define AOFF(lane) (((((lane) & 15) * PW + ((lane) >> 4) * 4)) << 2)
// B-fragment lane offset (two n-blocks of 8)
#define BOFF(lane) (((((((lane) >> 4) << 3) + ((lane) & 7)) * PW + (((lane) >> 3) & 1) * 4)) << 2)

// ---------------- positional encoding ----------------
__global__ void pe_kernel() {
    int idx = blockIdx.x * 256 + threadIdx.x;
    if (idx >= NR * 256) return;
    int r = idx >> 8;
    int m = idx & 255;
    float inv = exp2f(-(float)m * (13.287712379549449f / 256.0f));
    float ang = (float)(1023 - r) * inv;
    gPE[r * ND + 2 * m]     = (float)sin((double)ang);
    gPE[r * ND + 2 * m + 1] = (float)cos((double)ang);
}

// ---------------- GEMM body -------------------------------------------
struct ProjArgs {
    const float* A[4];
    const float* W[4];
    const float* bias[4];
    unsigned*    Ch[4];
    unsigned*    Cl[4];
    float*       Cf[4];
    int          M[4];
    int          split[4];
};

__device__ __forceinline__ void proj_body(const float* __restrict__ A,
                                          const float* __restrict__ W,
                                          const float* __restrict__ bias,
                                          unsigned* Ch, unsigned* Cl, float* Cf,
                                          int M, int do_split,
                                          int bx, int by, unsigned* sm) {
    unsigned* Ah = sm;                    // 128*PW
    unsigned* Al = Ah + 128 * PW;
    unsigned* Wh = Al + 128 * PW;         // 64*PW, stored [n][kword]
    unsigned* Wl = Wh + 64 * PW;
    int tid = threadIdx.x;
    int warp = tid >> 5, lane = tid & 31;
    int wm = warp >> 1, wn = warp & 1;
    int g = lane >> 2, t = lane & 3;
    int bm = by * 128, bn = bx * 64;
    float acc[2][4][4] = {};
    unsigned uAh = smaddr(Ah), uAl = smaddr(Al), uWh = smaddr(Wh), uWl = smaddr(Wl);
    unsigned aoff = AOFF(lane), boff = BOFF(lane);

    for (int k0 = 0; k0 < 512; k0 += 64) {
        #pragma unroll
        for (int i = 0; i < 8; i++) {
            int idx = tid + i * 256;
            int row = idx >> 4, c4 = (idx & 15) << 2;
            int grow = bm + row;
            float4 av = (grow < M) ? *(const float4*)&A[(size_t)grow * 512 + k0 + c4]
                                   : make_float4(0.f, 0.f, 0.f, 0.f);
            int w = c4 >> 1;
            unsigned h0, l0, h1, l1;
            cvt_pair2(av.x, av.y, h0, l0);
            cvt_pair2(av.z, av.w, h1, l1);
            *(uint2*)&Ah[row * PW + w] = make_uint2(h0, h1);
            *(uint2*)&Al[row * PW + w] = make_uint2(l0, l1);
        }
        #pragma unroll
        for (int i = 0; i < 4; i++) {
            int idx = tid + i * 256;
            int row = idx >> 4, c4 = (idx & 15) << 2;
            float4 wv = *(const float4*)&W[(size_t)(bn + row) * 512 + k0 + c4];
            int w = c4 >> 1;
            unsigned h0, l0, h1, l1;
            cvt_pair2(wv.x, wv.y, h0, l0);
            cvt_pair2(wv.z, wv.w, h1, l1);
            *(uint2*)&Wh[row * PW + w] = make_uint2(h0, h1);
            *(uint2*)&Wl[row * PW + w] = make_uint2(l0, l1);
        }
        __syncthreads();
        #pragma unroll
        for (int kw = 0; kw < 32; kw += 8) {
            unsigned ah[2][4], al[2][4];
            #pragma unroll
            for (int mt = 0; mt < 2; mt++) {
                unsigned base = (((wm * 32 + mt * 16) * PW + kw) << 2) + aoff;
                ldsm4(ah[mt][0], ah[mt][1], ah[mt][2], ah[mt][3], uAh + base);
                ldsm4(al[mt][0], al[mt][1], al[mt][2], al[mt][3], uAl + base);
            }
            #pragma unroll
            for (int pair = 0; pair < 2; pair++) {
                unsigned base = (((wn * 32 + pair * 16) * PW + kw) << 2) + boff;
                unsigned bh[4], bl[4];
                ldsm4(bh[0], bh[1], bh[2], bh[3], uWh + base);
                ldsm4(bl[0], bl[1], bl[2], bl[3], uWl + base);
                #pragma unroll
                for (int half = 0; half < 2; half++) {
                    int nt = pair * 2 + half;
                    unsigned bh0 = bh[half * 2], bh1 = bh[half * 2 + 1];
                    unsigned bl0 = bl[half * 2], bl1 = bl[half * 2 + 1];
                    #pragma unroll
                    for (int mt = 0; mt < 2; mt++) {
                        mma16(acc[mt][nt], ah[mt][0], ah[mt][1], ah[mt][2], ah[mt][3], bh0, bh1);
                        mma16(acc[mt][nt], ah[mt][0], ah[mt][1], ah[mt][2], ah[mt][3], bl0, bl1);
                        mma16(acc[mt][nt], al[mt][0], al[mt][1], al[mt][2], al[mt][3], bh0, bh1);
                    }
                }
            }
        }
        __syncthreads();
    }
    #pragma unroll
    for (int mt = 0; mt < 2; mt++) {
        #pragma unroll
        for (int nt = 0; nt < 4; nt++) {
            int row = bm + wm * 32 + mt * 16 + g;
            int col = bn + wn * 32 + nt * 8 + t * 2;
            float f0 = acc[mt][nt][0] + bias[col];
            float f1 = acc[mt][nt][1] + bias[col + 1];
            float f2 = acc[mt][nt][2] + bias[col];
            float f3 = acc[mt][nt][3] + bias[col + 1];
            if (do_split) {
                unsigned h0, l0;
                if (row < M) {
                    cvt_pair2(f0, f1, h0, l0);
                    Ch[(size_t)row * NW + (col >> 1)] = h0;
                    Cl[(size_t)row * NW + (col >> 1)] = l0;
                }
                if (row + 8 < M) {
                    cvt_pair2(f2, f3, h0, l0);
                    Ch[(size_t)(row + 8) * NW + (col >> 1)] = h0;
                    Cl[(size_t)(row + 8) * NW + (col >> 1)] = l0;
                }
            } else {
                if (row < M) {
                    Cf[(size_t)row * 512 + col]     = f0;
                    Cf[(size_t)row * 512 + col + 1] = f1;
                }
                if (row + 8 < M) {
                    Cf[(size_t)(row + 8) * 512 + col]     = f2;
                    Cf[(size_t)(row + 8) * 512 + col + 1] = f3;
                }
            }
        }
    }
}

__global__ void proj_all(ProjArgs a) {
    extern __shared__ unsigned sm[];
    int bid = blockIdx.x;
    int z, bx, by;
    if (bid < 768) { z = bid >> 8; int r = bid & 255; by = r >> 3; bx = r & 7; }
    else           { z = 3;        int r = bid - 768; by = r >> 3; bx = r & 7; }
    proj_body(a.A[z], a.W[z], a.bias[z], a.Ch[z], a.Cl[z], a.Cf[z], a.M[z], a.split[z],
              bx, by, sm);
}

__global__ void proj_out(const float* __restrict__ A, const float* __restrict__ W,
                         const float* __restrict__ bias, float* __restrict__ C, int M) {
    extern __shared__ unsigned sm[];
    proj_body(A, W, bias, 0, 0, C, M, 0, blockIdx.x, blockIdx.y, sm);
}

// ---------------- gUK + gVE fused (from split arrays) ------------------
__global__ void ukve_kernel(const float* __restrict__ u, const float* __restrict__ v) {
    int gid = blockIdx.x * 256 + threadIdx.x;
    int w = gid >> 5, lane = gid & 31;
    if (w < NB * NH * NT) {
        int t = w & (NT - 1);
        int bh = w >> 10;
        int h = bh & 7, b = bh >> 3;
        size_t base = (size_t)(b * NT + t) * NW + h * 32 + lane;
        float2 kh = unpack2(gKh[base]);
        float2 kl = unpack2(gKl[base]);
        const float* up = u + h * NDH;
        float s = (kh.x + kl.x) * up[2 * lane] + (kh.y + kl.y) * up[2 * lane + 1];
        #pragma unroll
        for (int o = 16; o; o >>= 1) s += __shfl_down_sync(0xffffffffu, s, o);
        if (lane == 0) gUK[bh * NT + t] = s;
    } else {
        int w2 = w - NB * NH * NT;
        if (w2 >= NH * NR) return;
        int h = w2 / NR;
        int r = w2 - h * NR;
        size_t base = (size_t)r * NW + h * 32 + lane;
        float2 eh = unpack2(gEh[base]);
        float2 el = unpack2(gEl[base]);
        const float* vp = v + h * NDH;
        float s = (eh.x + el.x) * vp[2 * lane] + (eh.y + el.y) * vp[2 * lane + 1];
        #pragma unroll
        for (int o = 16; o; o >>= 1) s += __shfl_down_sync(0xffffffffu, s, o);
        if (lane == 0) gVE[h * NR + r] = s;
    }
}

// ---------------- scores: 64q x 128k, single-pass fused GEMMs, 2 CTA/SM ---
// Dedicated buffers for K, E0, E1; Q fragments loaded once per kw step.
// Gs ALIASES the K/E0 buffers (dead after the MMA loop) -> smem 110 KB.
// __launch_bounds__(256,2) caps regs at 128 for 2 CTAs/SM.
__global__ void __launch_bounds__(256, 2) scores_tc() {
    extern __shared__ unsigned sm[];
    unsigned* Qh  = sm;                     // 64*PW
    unsigned* Ql  = Qh  + 64 * PW;
    unsigned* Kh  = Ql  + 64 * PW;          // 128*PW
    unsigned* Kl  = Kh  + 128 * PW;
    unsigned* E0h = Kl  + 128 * PW;         // 128*PW
    unsigned* E0l = E0h + 128 * PW;
    unsigned* E1h = E0l + 128 * PW;         // 64*PW
    unsigned* E1l = E1h + 64 * PW;
    float* Gs   = (float*)Kh;               // ALIAS: 64*GSW floats over K/E0 area
    float* redM = (float*)(E1l + 64 * PW);  // [4][64]
    float* redL = redM + 256;               // [4][64]
    int tid = threadIdx.x;
    int bh = blockIdx.z, h = bh & 7, b = bh >> 3;
    int q0 = blockIdx.y * 64, k0 = blockIdx.x * 128;
    int warp = tid >> 5, lane = tid & 31;
    int wm = warp >> 2, wn = warp & 3;
    int g = lane >> 2, t = lane & 3;
    unsigned uQh = smaddr(Qh), uQl = smaddr(Ql);
    unsigned uKh = smaddr(Kh), uKl = smaddr(Kl);
    unsigned uE0h = smaddr(E0h), uE0l = smaddr(E0l);
    unsigned uE1h = smaddr(E1h), uE1l = smaddr(E1l);
    unsigned aoff = AOFF(lane), boff = BOFF(lane);
    int rbase = 960 + k0 - q0;   // >= 0 always; r = rbase + c, c = k + 63 - q
    const uint4 zero4 = make_uint4(0, 0, 0, 0);

    // ---- load ALL tiles: Q(64), K(128), E0(128), E1(64) ----
    #pragma unroll
    for (int i = 0; i < 2; i++) {
        int idx = tid + i * 256;
        int row = idx >> 3, w4 = (idx & 7) << 2;
        size_t gbase = (size_t)(b * NT + q0 + row) * NW + h * 32 + w4;
        *(uint4*)&Qh[row * PW + w4] = *(const uint4*)&gQh[gbase];
        *(uint4*)&Ql[row * PW + w4] = *(const uint4*)&gQl[gbase];
    }
    #pragma unroll
    for (int i = 0; i < 4; i++) {
        int idx = tid + i * 256;
        int row = idx >> 3, w4 = (idx & 7) << 2;
        size_t gbase = (size_t)(b * NT + k0 + row) * NW + h * 32 + w4;
        *(uint4*)&Kh[row * PW + w4] = *(const uint4*)&gKh[gbase];
        *(uint4*)&Kl[row * PW + w4] = *(const uint4*)&gKl[gbase];
    }
    #pragma unroll
    for (int i = 0; i < 4; i++) {
        int idx = tid + i * 256;
        int row = idx >> 3, w4 = (idx & 7) << 2;
        int r = rbase + row;
        size_t gbase = (size_t)r * NW + h * 32 + w4;
        *(uint4*)&E0h[row * PW + w4] = (r < NR) ? *(const uint4*)&gEh[gbase] : zero4;
        *(uint4*)&E0l[row * PW + w4] = (r < NR) ? *(const uint4*)&gEl[gbase] : zero4;
    }
    #pragma unroll
    for (int i = 0; i < 2; i++) {
        int idx = tid + i * 256;
        int row = idx >> 3, w4 = (idx & 7) << 2;
        int r = rbase + 128 + row;
        size_t gbase = (size_t)r * NW + h * 32 + w4;
        *(uint4*)&E1h[row * PW + w4] = (r < NR) ? *(const uint4*)&gEh[gbase] : zero4;
        *(uint4*)&E1l[row * PW + w4] = (r < NR) ? *(const uint4*)&gEl[gbase] : zero4;
    }
    __syncthreads();

    // ---- fused GEMM loop: Q fragments loaded once per kw step ----
    float accK[2][4][4] = {};
    float accE[2][4][4] = {};
    float accF[2][2][4] = {};
    #pragma unroll
    for (int kw = 0; kw < 32; kw += 8) {
        unsigned ah[2][4], al[2][4];
        #pragma unroll
        for (int mt = 0; mt < 2; mt++) {
            unsigned base = (((wm * 32 + mt * 16) * PW + kw) << 2) + aoff;
            ldsm4(ah[mt][0], ah[mt][1], ah[mt][2], ah[mt][3], uQh + base);
            ldsm4(al[mt][0], al[mt][1], al[mt][2], al[mt][3], uQl + base);
        }
        // QK
        #pragma unroll
        for (int pair = 0; pair < 2; pair++) {
            unsigned base = (((wn * 32 + pair * 16) * PW + kw) << 2) + boff;
            unsigned bhv[4], blv[4];
            ldsm4(bhv[0], bhv[1], bhv[2], bhv[3], uKh + base);
            ldsm4(blv[0], blv[1], blv[2], blv[3], uKl + base);
            #pragma unroll
            for (int half = 0; half < 2; half++) {
                int nt = pair * 2 + half;
                #pragma unroll
                for (int mt = 0; mt < 2; mt++) {
                    mma16(accK[mt][nt], ah[mt][0], ah[mt][1], ah[mt][2], ah[mt][3],
                          bhv[half*2], bhv[half*2+1]);
                    mma16(accK[mt][nt], ah[mt][0], ah[mt][1], ah[mt][2], ah[mt][3],
                          blv[half*2], blv[half*2+1]);
                    mma16(accK[mt][nt], al[mt][0], al[mt][1], al[mt][2], al[mt][3],
                          bhv[half*2], bhv[half*2+1]);
                }
            }
        }
        // E0
        #pragma unroll
        for (int pair = 0; pair < 2; pair++) {
            unsigned base = (((wn * 32 + pair * 16) * PW + kw) << 2) + boff;
            unsigned bhv[4], blv[4];
            ldsm4(bhv[0], bhv[1], bhv[2], bhv[3], uE0h + base);
            ldsm4(blv[0], blv[1], blv[2], blv[3], uE0l + base);
            #pragma unroll
            for (int half = 0; half < 2; half++) {
                int nt = pair * 2 + half;
                #pragma unroll
                for (int mt = 0; mt < 2; mt++) {
                    mma16(accE[mt][nt], ah[mt][0], ah[mt][1], ah[mt][2], ah[mt][3],
                          bhv[half*2], bhv[half*2+1]);
                    mma16(accE[mt][nt], ah[mt][0], ah[mt][1], ah[mt][2], ah[mt][3],
                          blv[half*2], blv[half*2+1]);
                    mma16(accE[mt][nt], al[mt][0], al[mt][1], al[mt][2], al[mt][3],
                          bhv[half*2], bhv[half*2+1]);
                }
            }
        }
        // E1 (warp n-width 16)
        {
            unsigned base = (((wn * 16) * PW + kw) << 2) + boff;
            unsigned bhv[4], blv[4];
            ldsm4(bhv[0], bhv[1], bhv[2], bhv[3], uE1h + base);
            ldsm4(blv[0], blv[1], blv[2], blv[3], uE1l + base);
            #pragma unroll
            for (int half = 0; half < 2; half++) {
                #pragma unroll
                for (int mt = 0; mt < 2; mt++) {
                    mma16(accF[mt][half], ah[mt][0], ah[mt][1], ah[mt][2], ah[mt][3],
                          bhv[half*2], bhv[half*2+1]);
                    mma16(accF[mt][half], ah[mt][0], ah[mt][1], ah[mt][2], ah[mt][3],
                          blv[half*2], blv[half*2+1]);
                    mma16(accF[mt][half], al[mt][0], al[mt][1], al[mt][2], al[mt][3],
                          bhv[half*2], bhv[half*2+1]);
                }
            }
        }
    }
    __syncthreads();   // all ldsm reads done before Gs overwrites K/E0 region

    // ---- write E results to Gs (aliased) ----
    #pragma unroll
    for (int mt = 0; mt < 2; mt++)
        #pragma unroll
        for (int nt = 0; nt < 4; nt++) {
            int row = wm * 32 + mt * 16 + g;
            int col = wn * 32 + nt * 8 + t * 2;
            Gs[row * GSW + col]           = accE[mt][nt][0];
            Gs[row * GSW + col + 1]       = accE[mt][nt][1];
            Gs[(row + 8) * GSW + col]     = accE[mt][nt][2];
            Gs[(row + 8) * GSW + col + 1] = accE[mt][nt][3];
        }
    #pragma unroll
    for (int mt = 0; mt < 2; mt++)
        #pragma unroll
        for (int nt = 0; nt < 2; nt++) {
            int row = wm * 32 + mt * 16 + g;
            int col = 128 + wn * 16 + nt * 8 + t * 2;
            Gs[row * GSW + col]           = accF[mt][nt][0];
            Gs[row * GSW + col + 1]       = accF[mt][nt][1];
            Gs[(row + 8) * GSW + col]     = accF[mt][nt][2];
            Gs[(row + 8) * GSW + col + 1] = accF[mt][nt][3];
        }
    __syncthreads();

    // ---- gather full raw scores ----
    #pragma unroll
    for (int mt = 0; mt < 2; mt++)
        #pragma unroll
        for (int nt = 0; nt < 4; nt++) {
            int kb = wn * 32 + nt * 8 + t * 2;
            #pragma unroll
            for (int r4 = 0; r4 < 4; r4++) {
                int q = wm * 32 + mt * 16 + g + ((r4 >= 2) ? 8 : 0);
                int k = kb + (r4 & 1);
                int c = k + 63 - q;
                accK[mt][nt][r4] = (accK[mt][nt][r4] + Gs[q * GSW + c]
                                    + gUK[bh * NT + k0 + k] + gVE[h * NR + rbase + c]) * 0.125f;
            }
        }

    // ---- per-tile row stats ----
    float mrow[2][2];
    #pragma unroll
    for (int mt = 0; mt < 2; mt++) {
        mrow[mt][0] = -1e30f; mrow[mt][1] = -1e30f;
        #pragma unroll
        for (int nt = 0; nt < 4; nt++) {
            mrow[mt][0] = fmaxf(mrow[mt][0], fmaxf(accK[mt][nt][0], accK[mt][nt][1]));
            mrow[mt][1] = fmaxf(mrow[mt][1], fmaxf(accK[mt][nt][2], accK[mt][nt][3]));
        }
        #pragma unroll
        for (int hf = 0; hf < 2; hf++) {
            mrow[mt][hf] = fmaxf(mrow[mt][hf], __shfl_xor_sync(0xffffffffu, mrow[mt][hf], 1));
            mrow[mt][hf] = fmaxf(mrow[mt][hf], __shfl_xor_sync(0xffffffffu, mrow[mt][hf], 2));
        }
    }
    if (t == 0) {
        #pragma unroll
        for (int mt = 0; mt < 2; mt++)
            #pragma unroll
            for (int hf = 0; hf < 2; hf++)
                redM[wn * 64 + wm * 32 + mt * 16 + g + hf * 8] = mrow[mt][hf];
    }
    __syncthreads();
    #pragma unroll
    for (int mt = 0; mt < 2; mt++)
        #pragma unroll
        for (int hf = 0; hf < 2; hf++) {
            int row = wm * 32 + mt * 16 + g + hf * 8;
            mrow[mt][hf] = fmaxf(fmaxf(redM[row], redM[64 + row]),
                                 fmaxf(redM[128 + row], redM[192 + row]));
        }

    float srow[2][2] = {};
    #pragma unroll
    for (int mt = 0; mt < 2; mt++)
        #pragma unroll
        for (int nt = 0; nt < 4; nt++) {
            accK[mt][nt][0] = __expf(accK[mt][nt][0] - mrow[mt][0]);
            accK[mt][nt][1] = __expf(accK[mt][nt][1] - mrow[mt][0]);
            accK[mt][nt][2] = __expf(accK[mt][nt][2] - mrow[mt][1]);
            accK[mt][nt][3] = __expf(accK[mt][nt][3] - mrow[mt][1]);
            srow[mt][0] += accK[mt][nt][0] + accK[mt][nt][1];
            srow[mt][1] += accK[mt][nt][2] + accK[mt][nt][3];
        }
    #pragma unroll
    for (int mt = 0; mt < 2; mt++)
        #pragma unroll
        for (int hf = 0; hf < 2; hf++) {
            srow[mt][hf] += __shfl_xor_sync(0xffffffffu, srow[mt][hf], 1);
            srow[mt][hf] += __shfl_xor_sync(0xffffffffu, srow[mt][hf], 2);
        }
    if (t == 0) {
        #pragma unroll
        for (int mt = 0; mt < 2; mt++)
            #pragma unroll
            for (int hf = 0; hf < 2; hf++)
                redL[wn * 64 + wm * 32 + mt * 16 + g + hf * 8] = srow[mt][hf];
    }
    __syncthreads();
    if (wn == 0 && t == 0) {
        #pragma unroll
        for (int mt = 0; mt < 2; mt++)
            #pragma unroll
            for (int hf = 0; hf < 2; hf++) {
                int row = wm * 32 + mt * 16 + g + hf * 8;
                size_t ri = (size_t)(bh * NT + q0 + row) * NKT + blockIdx.x;
                gPartM[ri] = mrow[mt][hf];
                gPartL[ri] = redL[row] + redL[64 + row] + redL[128 + row] + redL[192 + row];
            }
    }

    // ---- store exp values ----
    #pragma unroll
    for (int mt = 0; mt < 2; mt++)
        #pragma unroll
        for (int nt = 0; nt < 4; nt++) {
            int kb = wn * 32 + nt * 8 + t * 2;
            #pragma unroll
            for (int r4 = 0; r4 < 4; r4++) {
                int q = wm * 32 + mt * 16 + g + ((r4 >= 2) ? 8 : 0);
                int k = kb + (r4 & 1);
                gS[(size_t)(bh * NT + q0 + q) * NT + k0 + k] = accK[mt][nt][r4];
            }
        }
}

// ---------------- combine per-tile stats -> per-(row,tile) scales --------
__global__ void reduce_kernel() {
    int row = blockIdx.x * 256 + threadIdx.x;
    if (row >= NROWS) return;
    size_t base = (size_t)row * NKT;
    float m = -1e30f;
    float pm[NKT], pl[NKT];
    #pragma unroll
    for (int i = 0; i < NKT; i++) {
        pm[i] = gPartM[base + i];
        pl[i] = gPartL[base + i];
        m = fmaxf(m, pm[i]);
    }
    float l = 0.f;
    #pragma unroll
    for (int i = 0; i < NKT; i++) l += __expf(pm[i] - m) * pl[i];
    float inv = 1.f / l;
    #pragma unroll
    for (int i = 0; i < NKT; i++) gScale[base + i] = __expf(pm[i] - m) * inv;
}

// ---------------- O = P @ V: 128 thr, 4 warps, 32x32 warp tiles ----------
__global__ void pv_tc() {
    extern __shared__ unsigned sm[];
    unsigned* Ph  = sm;                   // 64*PW
    unsigned* Pl  = Ph + 64 * PW;
    unsigned* Vth = Pl + 64 * PW;         // 64*PW, [d][posword]
    unsigned* Vtl = Vth + 64 * PW;
    int tid = threadIdx.x;
    int warp = tid >> 5, lane = tid & 31;
    int wm = warp >> 1, wn = warp & 1;
    int g = lane >> 2, t = lane & 3;
    int bh = blockIdx.y, b = bh >> 3, h = bh & 7;
    int q0 = blockIdx.x * 64;
    float acc[2][4][4] = {};
    unsigned uPh = smaddr(Ph), uPl = smaddr(Pl), uVh = smaddr(Vth), uVl = smaddr(Vtl);
    unsigned aoff = AOFF(lane), boff = BOFF(lane);

    for (int kk0 = 0; kk0 < NT; kk0 += 64) {
        int kt8 = kk0 >> 7;
        #pragma unroll
        for (int i = 0; i < 8; i++) {
            int idx = tid + i * 128;
            int row = idx >> 4, c4 = (idx & 15) << 2;
            float sc = gScale[(size_t)(bh * NT + q0 + row) * NKT + kt8];
            float4 pv = *(const float4*)&gS[(size_t)(bh * NT + q0 + row) * NT + kk0 + c4];
            int w = c4 >> 1;
            unsigned h0, l0, h1, l1;
            cvt_pair2(pv.x * sc, pv.y * sc, h0, l0);
            cvt_pair2(pv.z * sc, pv.w * sc, h1, l1);
            *(uint2*)&Ph[row * PW + w] = make_uint2(h0, h1);
            *(uint2*)&Pl[row * PW + w] = make_uint2(l0, l1);
        }
        #pragma unroll
        for (int i = 0; i < 4; i++) {
            int u = tid + i * 128;
            int p = u >> 4, dg = (u & 15) << 2;
            const float* v0 = &gV[(size_t)(b * NT + kk0 + 2 * p) * ND + h * NDH + dg];
            const float* v1 = v0 + ND;
            float4 a = *(const float4*)v0;
            float4 c = *(const float4*)v1;
            unsigned hv, lv;
            cvt_pair2(a.x, c.x, hv, lv); Vth[(dg + 0) * PW + p] = hv; Vtl[(dg + 0) * PW + p] = lv;
            cvt_pair2(a.y, c.y, hv, lv); Vth[(dg + 1) * PW + p] = hv; Vtl[(dg + 1) * PW + p] = lv;
            cvt_pair2(a.z, c.z, hv, lv); Vth[(dg + 2) * PW + p] = hv; Vtl[(dg + 2) * PW + p] = lv;
            cvt_pair2(a.w, c.w, hv, lv); Vth[(dg + 3) * PW + p] = hv; Vtl[(dg + 3) * PW + p] = lv;
        }
        __syncthreads();
        #pragma unroll
        for (int kw = 0; kw < 32; kw += 8) {
            unsigned ah[2][4], al[2][4];
            #pragma unroll
            for (int mt = 0; mt < 2; mt++) {
                unsigned base = (((wm * 32 + mt * 16) * PW + kw) << 2) + aoff;
                ldsm4(ah[mt][0], ah[mt][1], ah[mt][2], ah[mt][3], uPh + base);
                ldsm4(al[mt][0], al[mt][1], al[mt][2], al[mt][3], uPl + base);
            }
            #pragma unroll
            for (int pair = 0; pair < 2; pair++) {
                unsigned base = (((wn * 32 + pair * 16) * PW + kw) << 2) + boff;
                unsigned bhv[4], blv[4];
                ldsm4(bhv[0], bhv[1], bhv[2], bhv[3], uVh + base);
                ldsm4(blv[0], blv[1], blv[2], blv[3], uVl + base);
                #pragma unroll
                for (int half = 0; half < 2; half++) {
                    int nt = pair * 2 + half;
                    #pragma unroll
                    for (int mt = 0; mt < 2; mt++) {
                        mma16(acc[mt][nt], ah[mt][0], ah[mt][1], ah[mt][2], ah[mt][3],
                              bhv[half*2], bhv[half*2+1]);
                        mma16(acc[mt][nt], ah[mt][0], ah[mt][1], ah[mt][2], ah[mt][3],
                              blv[half*2], blv[half*2+1]);
                        mma16(acc[mt][nt], al[mt][0], al[mt][1], al[mt][2], al[mt][3],
                              bhv[half*2], bhv[half*2+1]);
                    }
                }
            }
        }
        __syncthreads();
    }
    #pragma unroll
    for (int mt = 0; mt < 2; mt++)
        #pragma unroll
        for (int nt = 0; nt < 4; nt++) {
            int row = q0 + wm * 32 + mt * 16 + g;
            int col = wn * 32 + nt * 8 + t * 2;
            gO[(size_t)(b * NT + row) * ND + h * NDH + col]         = acc[mt][nt][0];
            gO[(size_t)(b * NT + row) * ND + h * NDH + col + 1]     = acc[mt][nt][1];
            gO[(size_t)(b * NT + row + 8) * ND + h * NDH + col]     = acc[mt][nt][2];
            gO[(size_t)(b * NT + row + 8) * ND + h * NDH + col + 1] = acc[mt][nt][3];
        }
}

// -------------------------------------------------------------------------
extern "C" void kernel_launch(void* const* d_in, const int* in_sizes, int n_in,
                              void* d_out, int out_size) {
    const float* query = (const float*)d_in[0];
    const float* key_  = (const float*)d_in[1];
    const float* value = (const float*)d_in[2];
    const float* Wq = (const float*)d_in[3];
    const float* bq = (const float*)d_in[4];
    const float* Wk = (const float*)d_in[5];
    const float* bk = (const float*)d_in[6];
    const float* Wv = (const float*)d_in[7];
    const float* bv = (const float*)d_in[8];
    const float* Wp = (const float*)d_in[9];
    const float* bp = (const float*)d_in[10];
    const float* Wo = (const float*)d_in[11];
    const float* bo = (const float*)d_in[12];
    const float* ub = (const float*)d_in[13];
    const float* vb = (const float*)d_in[14];
    float* out = (float*)d_out;

    unsigned *pQh, *pQl, *pKh, *pKl, *pEh, *pEl;
    float *pV, *pPE, *pO;
    cudaGetSymbolAddress((void**)&pQh, gQh);
    cudaGetSymbolAddress((void**)&pQl, gQl);
    cudaGetSymbolAddress((void**)&pKh, gKh);
    cudaGetSymbolAddress((void**)&pKl, gKl);
    cudaGetSymbolAddress((void**)&pEh, gEh);
    cudaGetSymbolAddress((void**)&pEl, gEl);
    cudaGetSymbolAddress((void**)&pV, gV);
    cudaGetSymbolAddress((void**)&pPE, gPE);
    cudaGetSymbolAddress((void**)&pO, gO);

    const int PROJ_SMEM   = (2 * 128 * PW + 2 * 64 * PW) * 4;                 // 55296
    const int SCORES_SMEM = (2 * PW * (64 + 128 + 128 + 64) + 512) * 4;       // 112640
    const int PV_SMEM     = (4 * 64 * PW) * 4;                                // 36864
    cudaFuncSetAttribute(proj_all,  cudaFuncAttributeMaxDynamicSharedMemorySize, PROJ_SMEM);
    cudaFuncSetAttribute(proj_out,  cudaFuncAttributeMaxDynamicSharedMemorySize, PROJ_SMEM);
    cudaFuncSetAttribute(scores_tc, cudaFuncAttributeMaxDynamicSharedMemorySize, SCORES_SMEM);
    cudaFuncSetAttribute(pv_tc,     cudaFuncAttributeMaxDynamicSharedMemorySize, PV_SMEM);

    ProjArgs pa;
    pa.A[0] = query; pa.W[0] = Wq; pa.bias[0] = bq; pa.M[0] = NM;
    pa.Ch[0] = pQh;  pa.Cl[0] = pQl; pa.Cf[0] = 0;  pa.split[0] = 1;
    pa.A[1] = key_;  pa.W[1] = Wk; pa.bias[1] = bk; pa.M[1] = NM;
    pa.Ch[1] = pKh;  pa.Cl[1] = pKl; pa.Cf[1] = 0;  pa.split[1] = 1;
    pa.A[2] = value; pa.W[2] = Wv; pa.bias[2] = bv; pa.M[2] = NM;
    pa.Ch[2] = 0;    pa.Cl[2] = 0;   pa.Cf[2] = pV; pa.split[2] = 0;
    pa.A[3] = pPE;   pa.W[3] = Wp; pa.bias[3] = bp; pa.M[3] = NR;
    pa.Ch[3] = pEh;  pa.Cl[3] = pEl; pa.Cf[3] = 0;  pa.split[3] = 1;

    pe_kernel<<<NR, 256>>>();
    proj_all<<<896, 256, PROJ_SMEM>>>(pa);
    ukve_kernel<<<6143, 256>>>(ub, vb);
    scores_tc<<<dim3(8, 16, 32), 256, SCORES_SMEM>>>();
    reduce_kernel<<<128, 256>>>();
    pv_tc<<<dim3(16, 32), 128, PV_SMEM>>>();
    proj_out<<<dim3(8, 32), 256, PROJ_SMEM>>>(pO, Wo, bo, out, NM);
}

// round 14
// speedup vs baseline: 1.2151x; 1.1159x over previous
#include <cuda_runtime.h>
#include <cuda_bf16.h>
#include <math.h>

// Problem shapes (fixed by the dataset)
#define NB 4
#define NT 1024
#define ND 512
#define NH 8
#define NDH 64
#define NR 2047          // 2*T - 1
#define NM 4096          // B*T
#define NROWS (NB * NH * NT)   // 32768 score rows
#define NKT 8                  // k-tiles of 128 per row
#define NW 256                 // words per row (512 floats / 2)
#define AW (NM * NW)           // words per split input tensor
#define WW (ND * NW)           // words per split weight matrix

#define PW 36            // padded word-row length (32 data words + 4)
#define GSW 196          // Gs row stride (191 cols + pad)

// ---------------- device scratch (no allocations allowed) ----------------
__device__ unsigned gAh[3 * AW];      // split inputs: query, key, value
__device__ unsigned gAl[3 * AW];
__device__ unsigned gWh[5 * WW];      // split weights: Wq, Wk, Wv, Wp, Wo
__device__ unsigned gWl[5 * WW];
__device__ unsigned gPEh[NR * NW];    // split positional encoding
__device__ unsigned gPEl[NR * NW];
__device__ unsigned gQh[NM * NW];
__device__ unsigned gQl[NM * NW];
__device__ unsigned gKh[NM * NW];
__device__ unsigned gKl[NM * NW];
__device__ unsigned gEh[NR * NW];
__device__ unsigned gEl[NR * NW];
__device__ float    gV[NM * ND];
__device__ unsigned gVth[NB * NH * 64 * 512];   // split V^T [bh][d][posword]
__device__ unsigned gVtl[NB * NH * 64 * 512];
__device__ unsigned gSh[(size_t)NROWS * 512];   // split exp(s - m_tile)
__device__ unsigned gSl[(size_t)NROWS * 512];
__device__ unsigned gOh[NM * NW];     // split attention output
__device__ unsigned gOl[NM * NW];
__device__ float gUK[NB * NH * NT];
__device__ float gVE[NH * NR];
__device__ float gPartM[NROWS * NKT];
__device__ float gPartL[NROWS * NKT];
__device__ float gScale[NROWS * NKT];

// ---------------- bf16 split helpers ----------------
__device__ __forceinline__ void cvt_pair2(float a, float b, unsigned& hi, unsigned& lo) {
    unsigned ha = __bfloat16_as_ushort(__float2bfloat16(a));
    unsigned hb = __bfloat16_as_ushort(__float2bfloat16(b));
    float ra = a - __bfloat162float(__ushort_as_bfloat16((unsigned short)ha));
    float rb = b - __bfloat162float(__ushort_as_bfloat16((unsigned short)hb));
    unsigned la = __bfloat16_as_ushort(__float2bfloat16(ra));
    unsigned lb = __bfloat16_as_ushort(__float2bfloat16(rb));
    hi = (hb << 16) | ha;
    lo = (lb << 16) | la;
}
__device__ __forceinline__ float2 unpack2(unsigned w) {
    return make_float2(__bfloat162float(__ushort_as_bfloat16((unsigned short)(w & 0xffff))),
                       __bfloat162float(__ushort_as_bfloat16((unsigned short)(w >> 16))));
}
__device__ __forceinline__ void mma16(float (&c)[4], unsigned a0, unsigned a1,
                                      unsigned a2, unsigned a3, unsigned b0, unsigned b1) {
    asm volatile(
        "mma.sync.aligned.m16n8k16.row.col.f32.bf16.bf16.f32 "
        "{%0,%1,%2,%3},{%4,%5,%6,%7},{%8,%9},{%0,%1,%2,%3};"
        : "+f"(c[0]), "+f"(c[1]), "+f"(c[2]), "+f"(c[3])
        : "r"(a0), "r"(a1), "r"(a2), "r"(a3), "r"(b0), "r"(b1));
}
__device__ __forceinline__ unsigned smaddr(const void* p) {
    return (unsigned)__cvta_generic_to_shared(p);
}
__device__ __forceinline__ void ldsm4(unsigned& r0, unsigned& r1, unsigned& r2,
                                      unsigned& r3, unsigned a) {
    asm volatile("ldmatrix.sync.aligned.m8n8.x4.shared.b16 {%0,%1,%2,%3}, [%4];"
                 : "=r"(r0), "=r"(r1), "=r"(r2), "=r"(r3) : "r"(a));
}
#define AOFF(lane) (((((lane) & 15) * PW + ((lane) >> 4) * 4)) << 2)
#define BOFF(lane) (((((((lane) >> 4) << 3) + ((lane) & 7)) * PW + (((lane) >> 3) & 1) * 4)) << 2)

// ---------------- positional encoding (emits split directly) --------------
__global__ void pe_kernel() {
    int idx = blockIdx.x * 256 + threadIdx.x;
    if (idx >= NR * 256) return;
    int r = idx >> 8;
    int m = idx & 255;
    float inv = exp2f(-(float)m * (13.287712379549449f / 256.0f));
    float ang = (float)(1023 - r) * inv;
    float s, c;
    sincosf(ang, &s, &c);
    unsigned h, l;
    cvt_pair2(s, c, h, l);
    gPEh[r * NW + m] = h;
    gPEl[r * NW + m] = l;
}

// ---------------- pre-split raw inputs + weights --------------------------
__global__ void presplit(const float* __restrict__ q, const float* __restrict__ k,
                         const float* __restrict__ v, const float* __restrict__ wq,
                         const float* __restrict__ wk, const float* __restrict__ wv,
                         const float* __restrict__ wp, const float* __restrict__ wo) {
    int idx = blockIdx.x * 256 + threadIdx.x;
    if (idx < 3 * AW) {
        int z = idx / AW, rem = idx - z * AW;
        const float* src = (z == 0) ? q : (z == 1) ? k : v;
        cvt_pair2(src[2 * rem], src[2 * rem + 1], gAh[idx], gAl[idx]);
    } else {
        int j = idx - 3 * AW;
        if (j >= 5 * WW) return;
        int z = j / WW, rem = j - z * WW;
        const float* src = (z == 0) ? wq : (z == 1) ? wk : (z == 2) ? wv
                         : (z == 3) ? wp : wo;
        cvt_pair2(src[2 * rem], src[2 * rem + 1], gWh[j], gWl[j]);
    }
}

// ---------------- V transpose + split: gV -> gVt --------------------------
__global__ void vt_kernel() {
    __shared__ float Vs[64][65];
    int bh = blockIdx.y, b = bh >> 3, h = bh & 7;
    int p0 = blockIdx.x * 64;
    int tid = threadIdx.x;
    #pragma unroll
    for (int i = 0; i < 16; i++) {
        int idx = tid + i * 256;
        int p = idx >> 6, d = idx & 63;
        Vs[p][d] = gV[(size_t)(b * NT + p0 + p) * ND + h * NDH + d];
    }
    __syncthreads();
    #pragma unroll
    for (int i = 0; i < 8; i++) {
        int idx = tid + i * 256;
        int d = idx >> 5, j = idx & 31;
        unsigned hv, lv;
        cvt_pair2(Vs[2 * j][d], Vs[2 * j + 1][d], hv, lv);
        gVth[(size_t)(bh * 64 + d) * 512 + (p0 >> 1) + j] = hv;
        gVtl[(size_t)(bh * 64 + d) * 512 + (p0 >> 1) + j] = lv;
    }
}

// ---------------- GEMM body (all operands pre-split) ----------------------
struct ProjArgs {
    const unsigned* Ah[4];
    const unsigned* Al[4];
    const unsigned* Wh[4];
    const unsigned* Wl[4];
    const float*    bias[4];
    unsigned*       Ch[4];
    unsigned*       Cl[4];
    float*          Cf[4];
    int             M[4];
    int             split[4];
};

__device__ __forceinline__ void proj_body(const unsigned* __restrict__ Agh,
                                          const unsigned* __restrict__ Agl,
                                          const unsigned* __restrict__ Wgh,
                                          const unsigned* __restrict__ Wgl,
                                          const float* __restrict__ bias,
                                          unsigned* Ch, unsigned* Cl, float* Cf,
                                          int M, int do_split,
                                          int bx, int by, unsigned* sm) {
    unsigned* Ah = sm;                    // 128*PW
    unsigned* Al = Ah + 128 * PW;
    unsigned* Wh = Al + 128 * PW;         // 64*PW
    unsigned* Wl = Wh + 64 * PW;
    int tid = threadIdx.x;
    int warp = tid >> 5, lane = tid & 31;
    int wm = warp >> 1, wn = warp & 1;
    int g = lane >> 2, t = lane & 3;
    int bm = by * 128, bn = bx * 64;
    float acc[2][4][4] = {};
    unsigned uAh = smaddr(Ah), uAl = smaddr(Al), uWh = smaddr(Wh), uWl = smaddr(Wl);
    unsigned aoff = AOFF(lane), boff = BOFF(lane);
    const uint4 zero4 = make_uint4(0, 0, 0, 0);

    for (int k0w = 0; k0w < 256; k0w += 32) {
        #pragma unroll
        for (int i = 0; i < 4; i++) {
            int idx = tid + i * 256;
            int row = idx >> 3, w4 = (idx & 7) << 2;
            int grow = bm + row;
            size_t gb = (size_t)grow * NW + k0w + w4;
            *(uint4*)&Ah[row * PW + w4] = (grow < M) ? *(const uint4*)&Agh[gb] : zero4;
            *(uint4*)&Al[row * PW + w4] = (grow < M) ? *(const uint4*)&Agl[gb] : zero4;
        }
        #pragma unroll
        for (int i = 0; i < 2; i++) {
            int idx = tid + i * 256;
            int row = idx >> 3, w4 = (idx & 7) << 2;
            size_t gb = (size_t)(bn + row) * NW + k0w + w4;
            *(uint4*)&Wh[row * PW + w4] = *(const uint4*)&Wgh[gb];
            *(uint4*)&Wl[row * PW + w4] = *(const uint4*)&Wgl[gb];
        }
        __syncthreads();
        #pragma unroll
        for (int kw = 0; kw < 32; kw += 8) {
            unsigned ah[2][4], al[2][4];
            #pragma unroll
            for (int mt = 0; mt < 2; mt++) {
                unsigned base = (((wm * 32 + mt * 16) * PW + kw) << 2) + aoff;
                ldsm4(ah[mt][0], ah[mt][1], ah[mt][2], ah[mt][3], uAh + base);
                ldsm4(al[mt][0], al[mt][1], al[mt][2], al[mt][3], uAl + base);
            }
            #pragma unroll
            for (int pair = 0; pair < 2; pair++) {
                unsigned base = (((wn * 32 + pair * 16) * PW + kw) << 2) + boff;
                unsigned bh[4], bl[4];
                ldsm4(bh[0], bh[1], bh[2], bh[3], uWh + base);
                ldsm4(bl[0], bl[1], bl[2], bl[3], uWl + base);
                #pragma unroll
                for (int half = 0; half < 2; half++) {
                    int nt = pair * 2 + half;
                    unsigned bh0 = bh[half * 2], bh1 = bh[half * 2 + 1];
                    unsigned bl0 = bl[half * 2], bl1 = bl[half * 2 + 1];
                    #pragma unroll
                    for (int mt = 0; mt < 2; mt++) {
                        mma16(acc[mt][nt], ah[mt][0], ah[mt][1], ah[mt][2], ah[mt][3], bh0, bh1);
                        mma16(acc[mt][nt], ah[mt][0], ah[mt][1], ah[mt][2], ah[mt][3], bl0, bl1);
                        mma16(acc[mt][nt], al[mt][0], al[mt][1], al[mt][2], al[mt][3], bh0, bh1);
                    }
                }
            }
        }
        __syncthreads();
    }
    #pragma unroll
    for (int mt = 0; mt < 2; mt++) {
        #pragma unroll
        for (int nt = 0; nt < 4; nt++) {
            int row = bm + wm * 32 + mt * 16 + g;
            int col = bn + wn * 32 + nt * 8 + t * 2;
            float f0 = acc[mt][nt][0] + bias[col];
            float f1 = acc[mt][nt][1] + bias[col + 1];
            float f2 = acc[mt][nt][2] + bias[col];
            float f3 = acc[mt][nt][3] + bias[col + 1];
            if (do_split) {
                unsigned h0, l0;
                if (row < M) {
                    cvt_pair2(f0, f1, h0, l0);
                    Ch[(size_t)row * NW + (col >> 1)] = h0;
                    Cl[(size_t)row * NW + (col >> 1)] = l0;
                }
                if (row + 8 < M) {
                    cvt_pair2(f2, f3, h0, l0);
                    Ch[(size_t)(row + 8) * NW + (col >> 1)] = h0;
                    Cl[(size_t)(row + 8) * NW + (col >> 1)] = l0;
                }
            } else {
                if (row < M) {
                    Cf[(size_t)row * 512 + col]     = f0;
                    Cf[(size_t)row * 512 + col + 1] = f1;
                }
                if (row + 8 < M) {
                    Cf[(size_t)(row + 8) * 512 + col]     = f2;
                    Cf[(size_t)(row + 8) * 512 + col + 1] = f3;
                }
            }
        }
    }
}

__global__ void proj_all(ProjArgs a) {
    extern __shared__ unsigned sm[];
    int bid = blockIdx.x;
    int z, bx, by;
    if (bid < 768) { z = bid >> 8; int r = bid & 255; by = r >> 3; bx = r & 7; }
    else           { z = 3;        int r = bid - 768; by = r >> 3; bx = r & 7; }
    proj_body(a.Ah[z], a.Al[z], a.Wh[z], a.Wl[z], a.bias[z],
              a.Ch[z], a.Cl[z], a.Cf[z], a.M[z], a.split[z], bx, by, sm);
}

__global__ void proj_out(const unsigned* __restrict__ Ah, const unsigned* __restrict__ Al,
                         const unsigned* __restrict__ Wh, const unsigned* __restrict__ Wl,
                         const float* __restrict__ bias, float* __restrict__ C, int M) {
    extern __shared__ unsigned sm[];
    proj_body(Ah, Al, Wh, Wl, bias, 0, 0, C, M, 0, blockIdx.x, blockIdx.y, sm);
}

// ---------------- gUK + gVE fused -------------------------------------
__global__ void ukve_kernel(const float* __restrict__ u, const float* __restrict__ v) {
    int gid = blockIdx.x * 256 + threadIdx.x;
    int w = gid >> 5, lane = gid & 31;
    if (w < NB * NH * NT) {
        int t = w & (NT - 1);
        int bh = w >> 10;
        int h = bh & 7, b = bh >> 3;
        size_t base = (size_t)(b * NT + t) * NW + h * 32 + lane;
        float2 kh = unpack2(gKh[base]);
        float2 kl = unpack2(gKl[base]);
        const float* up = u + h * NDH;
        float s = (kh.x + kl.x) * up[2 * lane] + (kh.y + kl.y) * up[2 * lane + 1];
        #pragma unroll
        for (int o = 16; o; o >>= 1) s += __shfl_down_sync(0xffffffffu, s, o);
        if (lane == 0) gUK[bh * NT + t] = s;
    } else {
        int w2 = w - NB * NH * NT;
        if (w2 >= NH * NR) return;
        int h = w2 / NR;
        int r = w2 - h * NR;
        size_t base = (size_t)r * NW + h * 32 + lane;
        float2 eh = unpack2(gEh[base]);
        float2 el = unpack2(gEl[base]);
        const float* vp = v + h * NDH;
        float s = (eh.x + el.x) * vp[2 * lane] + (eh.y + el.y) * vp[2 * lane + 1];
        #pragma unroll
        for (int o = 16; o; o >>= 1) s += __shfl_down_sync(0xffffffffu, s, o);
        if (lane == 0) gVE[h * NR + r] = s;
    }
}

// ---------------- scores: fused single-pass, split P output ---------------
__global__ void __launch_bounds__(256, 2) scores_tc() {
    extern __shared__ unsigned sm[];
    unsigned* Qh  = sm;                     // 64*PW
    unsigned* Ql  = Qh  + 64 * PW;
    unsigned* Kh  = Ql  + 64 * PW;          // 128*PW
    unsigned* Kl  = Kh  + 128 * PW;
    unsigned* E0h = Kl  + 128 * PW;         // 128*PW
    unsigned* E0l = E0h + 128 * PW;
    unsigned* E1h = E0l + 128 * PW;         // 64*PW
    unsigned* E1l = E1h + 64 * PW;
    float* Gs   = (float*)Kh;               // ALIAS over K/E0 area
    float* redM = (float*)(E1l + 64 * PW);  // [4][64]
    float* redL = redM + 256;               // [4][64]
    int tid = threadIdx.x;
    int bh = blockIdx.z, h = bh & 7, b = bh >> 3;
    int q0 = blockIdx.y * 64, k0 = blockIdx.x * 128;
    int warp = tid >> 5, lane = tid & 31;
    int wm = warp >> 2, wn = warp & 3;
    int g = lane >> 2, t = lane & 3;
    unsigned uQh = smaddr(Qh), uQl = smaddr(Ql);
    unsigned uKh = smaddr(Kh), uKl = smaddr(Kl);
    unsigned uE0h = smaddr(E0h), uE0l = smaddr(E0l);
    unsigned uE1h = smaddr(E1h), uE1l = smaddr(E1l);
    unsigned aoff = AOFF(lane), boff = BOFF(lane);
    int rbase = 960 + k0 - q0;
    const uint4 zero4 = make_uint4(0, 0, 0, 0);

    #pragma unroll
    for (int i = 0; i < 2; i++) {
        int idx = tid + i * 256;
        int row = idx >> 3, w4 = (idx & 7) << 2;
        size_t gbase = (size_t)(b * NT + q0 + row) * NW + h * 32 + w4;
        *(uint4*)&Qh[row * PW + w4] = *(const uint4*)&gQh[gbase];
        *(uint4*)&Ql[row * PW + w4] = *(const uint4*)&gQl[gbase];
    }
    #pragma unroll
    for (int i = 0; i < 4; i++) {
        int idx = tid + i * 256;
        int row = idx >> 3, w4 = (idx & 7) << 2;
        size_t gbase = (size_t)(b * NT + k0 + row) * NW + h * 32 + w4;
        *(uint4*)&Kh[row * PW + w4] = *(const uint4*)&gKh[gbase];
        *(uint4*)&Kl[row * PW + w4] = *(const uint4*)&gKl[gbase];
    }
    #pragma unroll
    for (int i = 0; i < 4; i++) {
        int idx = tid + i * 256;
        int row = idx >> 3, w4 = (idx & 7) << 2;
        int r = rbase + row;
        size_t gbase = (size_t)r * NW + h * 32 + w4;
        *(uint4*)&E0h[row * PW + w4] = (r < NR) ? *(const uint4*)&gEh[gbase] : zero4;
        *(uint4*)&E0l[row * PW + w4] = (r < NR) ? *(const uint4*)&gEl[gbase] : zero4;
    }
    #pragma unroll
    for (int i = 0; i < 2; i++) {
        int idx = tid + i * 256;
        int row = idx >> 3, w4 = (idx & 7) << 2;
        int r = rbase + 128 + row;
        size_t gbase = (size_t)r * NW + h * 32 + w4;
        *(uint4*)&E1h[row * PW + w4] = (r < NR) ? *(const uint4*)&gEh[gbase] : zero4;
        *(uint4*)&E1l[row * PW + w4] = (r < NR) ? *(const uint4*)&gEl[gbase] : zero4;
    }
    __syncthreads();

    float accK[2][4][4] = {};
    float accE[2][4][4] = {};
    float accF[2][2][4] = {};
    #pragma unroll
    for (int kw = 0; kw < 32; kw += 8) {
        unsigned ah[2][4], al[2][4];
        #pragma unroll
        for (int mt = 0; mt < 2; mt++) {
            unsigned base = (((wm * 32 + mt * 16) * PW + kw) << 2) + aoff;
            ldsm4(ah[mt][0], ah[mt][1], ah[mt][2], ah[mt][3], uQh + base);
            ldsm4(al[mt][0], al[mt][1], al[mt][2], al[mt][3], uQl + base);
        }
        #pragma unroll
        for (int pair = 0; pair < 2; pair++) {
            unsigned base = (((wn * 32 + pair * 16) * PW + kw) << 2) + boff;
            unsigned bhv[4], blv[4];
            ldsm4(bhv[0], bhv[1], bhv[2], bhv[3], uKh + base);
            ldsm4(blv[0], blv[1], blv[2], blv[3], uKl + base);
            #pragma unroll
            for (int half = 0; half < 2; half++) {
                int nt = pair * 2 + half;
                #pragma unroll
                for (int mt = 0; mt < 2; mt++) {
                    mma16(accK[mt][nt], ah[mt][0], ah[mt][1], ah[mt][2], ah[mt][3],
                          bhv[half*2], bhv[half*2+1]);
                    mma16(accK[mt][nt], ah[mt][0], ah[mt][1], ah[mt][2], ah[mt][3],
                          blv[half*2], blv[half*2+1]);
                    mma16(accK[mt][nt], al[mt][0], al[mt][1], al[mt][2], al[mt][3],
                          bhv[half*2], bhv[half*2+1]);
                }
            }
        }
        #pragma unroll
        for (int pair = 0; pair < 2; pair++) {
            unsigned base = (((wn * 32 + pair * 16) * PW + kw) << 2) + boff;
            unsigned bhv[4], blv[4];
            ldsm4(bhv[0], bhv[1], bhv[2], bhv[3], uE0h + base);
            ldsm4(blv[0], blv[1], blv[2], blv[3], uE0l + base);
            #pragma unroll
            for (int half = 0; half < 2; half++) {
                int nt = pair * 2 + half;
                #pragma unroll
                for (int mt = 0; mt < 2; mt++) {
                    mma16(accE[mt][nt], ah[mt][0], ah[mt][1], ah[mt][2], ah[mt][3],
                          bhv[half*2], bhv[half*2+1]);
                    mma16(accE[mt][nt], ah[mt][0], ah[mt][1], ah[mt][2], ah[mt][3],
                          blv[half*2], blv[half*2+1]);
                    mma16(accE[mt][nt], al[mt][0], al[mt][1], al[mt][2], al[mt][3],
                          bhv[half*2], bhv[half*2+1]);
                }
            }
        }
        {
            unsigned base = (((wn * 16) * PW + kw) << 2) + boff;
            unsigned bhv[4], blv[4];
            ldsm4(bhv[0], bhv[1], bhv[2], bhv[3], uE1h + base);
            ldsm4(blv[0], blv[1], blv[2], blv[3], uE1l + base);
            #pragma unroll
            for (int half = 0; half < 2; half++) {
                #pragma unroll
                for (int mt = 0; mt < 2; mt++) {
                    mma16(accF[mt][half], ah[mt][0], ah[mt][1], ah[mt][2], ah[mt][3],
                          bhv[half*2], bhv[half*2+1]);
                    mma16(accF[mt][half], ah[mt][0], ah[mt][1], ah[mt][2], ah[mt][3],
                          blv[half*2], blv[half*2+1]);
                    mma16(accF[mt][half], al[mt][0], al[mt][1], al[mt][2], al[mt][3],
                          bhv[half*2], bhv[half*2+1]);
                }
            }
        }
    }
    __syncthreads();

    #pragma unroll
    for (int mt = 0; mt < 2; mt++)
        #pragma unroll
        for (int nt = 0; nt < 4; nt++) {
            int row = wm * 32 + mt * 16 + g;
            int col = wn * 32 + nt * 8 + t * 2;
            Gs[row * GSW + col]           = accE[mt][nt][0];
            Gs[row * GSW + col + 1]       = accE[mt][nt][1];
            Gs[(row + 8) * GSW + col]     = accE[mt][nt][2];
            Gs[(row + 8) * GSW + col + 1] = accE[mt][nt][3];
        }
    #pragma unroll
    for (int mt = 0; mt < 2; mt++)
        #pragma unroll
        for (int nt = 0; nt < 2; nt++) {
            int row = wm * 32 + mt * 16 + g;
            int col = 128 + wn * 16 + nt * 8 + t * 2;
            Gs[row * GSW + col]           = accF[mt][nt][0];
            Gs[row * GSW + col + 1]       = accF[mt][nt][1];
            Gs[(row + 8) * GSW + col]     = accF[mt][nt][2];
            Gs[(row + 8) * GSW + col + 1] = accF[mt][nt][3];
        }
    __syncthreads();

    #pragma unroll
    for (int mt = 0; mt < 2; mt++)
        #pragma unroll
        for (int nt = 0; nt < 4; nt++) {
            int kb = wn * 32 + nt * 8 + t * 2;
            #pragma unroll
            for (int r4 = 0; r4 < 4; r4++) {
                int q = wm * 32 + mt * 16 + g + ((r4 >= 2) ? 8 : 0);
                int k = kb + (r4 & 1);
                int c = k + 63 - q;
                accK[mt][nt][r4] = (accK[mt][nt][r4] + Gs[q * GSW + c]
                                    + gUK[bh * NT + k0 + k] + gVE[h * NR + rbase + c]) * 0.125f;
            }
        }

    float mrow[2][2];
    #pragma unroll
    for (int mt = 0; mt < 2; mt++) {
        mrow[mt][0] = -1e30f; mrow[mt][1] = -1e30f;
        #pragma unroll
        for (int nt = 0; nt < 4; nt++) {
            mrow[mt][0] = fmaxf(mrow[mt][0], fmaxf(accK[mt][nt][0], accK[mt][nt][1]));
            mrow[mt][1] = fmaxf(mrow[mt][1], fmaxf(accK[mt][nt][2], accK[mt][nt][3]));
        }
        #pragma unroll
        for (int hf = 0; hf < 2; hf++) {
            mrow[mt][hf] = fmaxf(mrow[mt][hf], __shfl_xor_sync(0xffffffffu, mrow[mt][hf], 1));
            mrow[mt][hf] = fmaxf(mrow[mt][hf], __shfl_xor_sync(0xffffffffu, mrow[mt][hf], 2));
        }
    }
    if (t == 0) {
        #pragma unroll
        for (int mt = 0; mt < 2; mt++)
            #pragma unroll
            for (int hf = 0; hf < 2; hf++)
                redM[wn * 64 + wm * 32 + mt * 16 + g + hf * 8] = mrow[mt][hf];
    }
    __syncthreads();
    #pragma unroll
    for (int mt = 0; mt < 2; mt++)
        #pragma unroll
        for (int hf = 0; hf < 2; hf++) {
            int row = wm * 32 + mt * 16 + g + hf * 8;
            mrow[mt][hf] = fmaxf(fmaxf(redM[row], redM[64 + row]),
                                 fmaxf(redM[128 + row], redM[192 + row]));
        }

    float srow[2][2] = {};
    #pragma unroll
    for (int mt = 0; mt < 2; mt++)
        #pragma unroll
        for (int nt = 0; nt < 4; nt++) {
            accK[mt][nt][0] = __expf(accK[mt][nt][0] - mrow[mt][0]);
            accK[mt][nt][1] = __expf(accK[mt][nt][1] - mrow[mt][0]);
            accK[mt][nt][2] = __expf(accK[mt][nt][2] - mrow[mt][1]);
            accK[mt][nt][3] = __expf(accK[mt][nt][3] - mrow[mt][1]);
            srow[mt][0] += accK[mt][nt][0] + accK[mt][nt][1];
            srow[mt][1] += accK[mt][nt][2] + accK[mt][nt][3];
        }
    #pragma unroll
    for (int mt = 0; mt < 2; mt++)
        #pragma unroll
        for (int hf = 0; hf < 2; hf++) {
            srow[mt][hf] += __shfl_xor_sync(0xffffffffu, srow[mt][hf], 1);
            srow[mt][hf] += __shfl_xor_sync(0xffffffffu, srow[mt][hf], 2);
        }
    if (t == 0) {
        #pragma unroll
        for (int mt = 0; mt < 2; mt++)
            #pragma unroll
            for (int hf = 0; hf < 2; hf++)
                redL[wn * 64 + wm * 32 + mt * 16 + g + hf * 8] = srow[mt][hf];
    }
    __syncthreads();
    if (wn == 0 && t == 0) {
        #pragma unroll
        for (int mt = 0; mt < 2; mt++)
            #pragma unroll
            for (int hf = 0; hf < 2; hf++) {
                int row = wm * 32 + mt * 16 + g + hf * 8;
                size_t ri = (size_t)(bh * NT + q0 + row) * NKT + blockIdx.x;
                gPartM[ri] = mrow[mt][hf];
                gPartL[ri] = redL[row] + redL[64 + row] + redL[128 + row] + redL[192 + row];
            }
    }

    // ---- store SPLIT exp values ----
    #pragma unroll
    for (int mt = 0; mt < 2; mt++)
        #pragma unroll
        for (int nt = 0; nt < 4; nt++) {
            int kb = wn * 32 + nt * 8 + t * 2;
            int row0 = wm * 32 + mt * 16 + g;
            unsigned h0, l0;
            cvt_pair2(accK[mt][nt][0], accK[mt][nt][1], h0, l0);
            size_t w0 = (size_t)(bh * NT + q0 + row0) * 512 + ((k0 + kb) >> 1);
            gSh[w0] = h0; gSl[w0] = l0;
            cvt_pair2(accK[mt][nt][2], accK[mt][nt][3], h0, l0);
            size_t w1 = (size_t)(bh * NT + q0 + row0 + 8) * 512 + ((k0 + kb) >> 1);
            gSh[w1] = h0; gSl[w1] = l0;
        }
}

// ---------------- combine per-tile stats -> per-(row,tile) scales --------
__global__ void reduce_kernel() {
    int row = blockIdx.x * 256 + threadIdx.x;
    if (row >= NROWS) return;
    size_t base = (size_t)row * NKT;
    float m = -1e30f;
    float pm[NKT], pl[NKT];
    #pragma unroll
    for (int i = 0; i < NKT; i++) {
        pm[i] = gPartM[base + i];
        pl[i] = gPartL[base + i];
        m = fmaxf(m, pm[i]);
    }
    float l = 0.f;
    #pragma unroll
    for (int i = 0; i < NKT; i++) l += __expf(pm[i] - m) * pl[i];
    float inv = 1.f / l;
    #pragma unroll
    for (int i = 0; i < NKT; i++) gScale[base + i] = __expf(pm[i] - m) * inv;
}

// ---------------- O = P @ V: pure copies, scale after tile GEMM ----------
__global__ void pv_tc() {
    extern __shared__ unsigned sm[];
    unsigned* Ph  = sm;                   // 64*PW
    unsigned* Pl  = Ph + 64 * PW;
    unsigned* Vth = Pl + 64 * PW;         // 64*PW, [d][posword]
    unsigned* Vtl = Vth + 64 * PW;
    int tid = threadIdx.x;
    int warp = tid >> 5, lane = tid & 31;
    int wm = warp >> 1, wn = warp & 1;
    int g = lane >> 2, t = lane & 3;
    int bh = blockIdx.y, b = bh >> 3;
    int q0 = blockIdx.x * 64;
    float acc[2][4][4] = {};
    unsigned uPh = smaddr(Ph), uPl = smaddr(Pl), uVh = smaddr(Vth), uVl = smaddr(Vtl);
    unsigned aoff = AOFF(lane), boff = BOFF(lane);

    for (int kk0w = 0; kk0w < 512; kk0w += 32) {
        int kt = kk0w >> 6;
        #pragma unroll
        for (int i = 0; i < 4; i++) {
            int idx = tid + i * 128;
            int row = idx >> 3, w4 = (idx & 7) << 2;
            size_t pb = (size_t)(bh * NT + q0 + row) * 512 + kk0w + w4;
            *(uint4*)&Ph[row * PW + w4] = *(const uint4*)&gSh[pb];
            *(uint4*)&Pl[row * PW + w4] = *(const uint4*)&gSl[pb];
        }
        #pragma unroll
        for (int i = 0; i < 4; i++) {
            int idx = tid + i * 128;
            int row = idx >> 3, w4 = (idx & 7) << 2;
            size_t vb = (size_t)(bh * 64 + row) * 512 + kk0w + w4;
            *(uint4*)&Vth[row * PW + w4] = *(const uint4*)&gVth[vb];
            *(uint4*)&Vtl[row * PW + w4] = *(const uint4*)&gVtl[vb];
        }
        __syncthreads();
        float ta[2][4][4] = {};
        #pragma unroll
        for (int kw = 0; kw < 32; kw += 8) {
            unsigned ah[2][4], al[2][4];
            #pragma unroll
            for (int mt = 0; mt < 2; mt++) {
                unsigned base = (((wm * 32 + mt * 16) * PW + kw) << 2) + aoff;
                ldsm4(ah[mt][0], ah[mt][1], ah[mt][2], ah[mt][3], uPh + base);
                ldsm4(al[mt][0], al[mt][1], al[mt][2], al[mt][3], uPl + base);
            }
            #pragma unroll
            for (int pair = 0; pair < 2; pair++) {
                unsigned base = (((wn * 32 + pair * 16) * PW + kw) << 2) + boff;
                unsigned bhv[4], blv[4];
                ldsm4(bhv[0], bhv[1], bhv[2], bhv[3], uVh + base);
                ldsm4(blv[0], blv[1], blv[2], blv[3], uVl + base);
                #pragma unroll
                for (int half = 0; half < 2; half++) {
                    int nt = pair * 2 + half;
                    #pragma unroll
                    for (int mt = 0; mt < 2; mt++) {
                        mma16(ta[mt][nt], ah[mt][0], ah[mt][1], ah[mt][2], ah[mt][3],
                              bhv[half*2], bhv[half*2+1]);
                        mma16(ta[mt][nt], ah[mt][0], ah[mt][1], ah[mt][2], ah[mt][3],
                              blv[half*2], blv[half*2+1]);
                        mma16(ta[mt][nt], al[mt][0], al[mt][1], al[mt][2], al[mt][3],
                              bhv[half*2], bhv[half*2+1]);
                    }
                }
            }
        }
        __syncthreads();
        float s0[2], s1[2];
        #pragma unroll
        for (int mt = 0; mt < 2; mt++) {
            s0[mt] = gScale[(size_t)(bh * NT + q0 + wm * 32 + mt * 16 + g) * NKT + kt];
            s1[mt] = gScale[(size_t)(bh * NT + q0 + wm * 32 + mt * 16 + g + 8) * NKT + kt];
        }
        #pragma unroll
        for (int mt = 0; mt < 2; mt++)
            #pragma unroll
            for (int nt = 0; nt < 4; nt++) {
                acc[mt][nt][0] += s0[mt] * ta[mt][nt][0];
                acc[mt][nt][1] += s0[mt] * ta[mt][nt][1];
                acc[mt][nt][2] += s1[mt] * ta[mt][nt][2];
                acc[mt][nt][3] += s1[mt] * ta[mt][nt][3];
            }
    }
    int h = bh & 7;
    #pragma unroll
    for (int mt = 0; mt < 2; mt++)
        #pragma unroll
        for (int nt = 0; nt < 4; nt++) {
            int row = q0 + wm * 32 + mt * 16 + g;
            int col = wn * 32 + nt * 8 + t * 2;
            unsigned hv, lv;
            cvt_pair2(acc[mt][nt][0], acc[mt][nt][1], hv, lv);
            size_t w0 = (size_t)(b * NT + row) * NW + h * 32 + (col >> 1);
            gOh[w0] = hv; gOl[w0] = lv;
            cvt_pair2(acc[mt][nt][2], acc[mt][nt][3], hv, lv);
            size_t w1 = (size_t)(b * NT + row + 8) * NW + h * 32 + (col >> 1);
            gOh[w1] = hv; gOl[w1] = lv;
        }
}

// -------------------------------------------------------------------------
extern "C" void kernel_launch(void* const* d_in, const int* in_sizes, int n_in,
                              void* d_out, int out_size) {
    const float* query = (const float*)d_in[0];
    const float* key_  = (const float*)d_in[1];
    const float* value = (const float*)d_in[2];
    const float* Wq = (const float*)d_in[3];
    const float* bq = (const float*)d_in[4];
    const float* Wk = (const float*)d_in[5];
    const float* bk = (const float*)d_in[6];
    const float* Wv = (const float*)d_in[7];
    const float* bv = (const float*)d_in[8];
    const float* Wp = (const float*)d_in[9];
    const float* bp = (const float*)d_in[10];
    const float* Wo = (const float*)d_in[11];
    const float* bo = (const float*)d_in[12];
    const float* ub = (const float*)d_in[13];
    const float* vb = (const float*)d_in[14];
    float* out = (float*)d_out;

    unsigned *pAh, *pAl, *pWh, *pWl, *pPEh, *pPEl;
    unsigned *pQh, *pQl, *pKh, *pKl, *pEh, *pEl, *pOh, *pOl;
    float *pV;
    cudaGetSymbolAddress((void**)&pAh, gAh);
    cudaGetSymbolAddress((void**)&pAl, gAl);
    cudaGetSymbolAddress((void**)&pWh, gWh);
    cudaGetSymbolAddress((void**)&pWl, gWl);
    cudaGetSymbolAddress((void**)&pPEh, gPEh);
    cudaGetSymbolAddress((void**)&pPEl, gPEl);
    cudaGetSymbolAddress((void**)&pQh, gQh);
    cudaGetSymbolAddress((void**)&pQl, gQl);
    cudaGetSymbolAddress((void**)&pKh, gKh);
    cudaGetSymbolAddress((void**)&pKl, gKl);
    cudaGetSymbolAddress((void**)&pEh, gEh);
    cudaGetSymbolAddress((void**)&pEl, gEl);
    cudaGetSymbolAddress((void**)&pOh, gOh);
    cudaGetSymbolAddress((void**)&pOl, gOl);
    cudaGetSymbolAddress((void**)&pV, gV);

    const int PROJ_SMEM   = (2 * 128 * PW + 2 * 64 * PW) * 4;                 // 55296
    const int SCORES_SMEM = (2 * PW * (64 + 128 + 128 + 64) + 512) * 4;       // 112640
    const int PV_SMEM     = (4 * 64 * PW) * 4;                                // 36864
    cudaFuncSetAttribute(proj_all,  cudaFuncAttributeMaxDynamicSharedMemorySize, PROJ_SMEM);
    cudaFuncSetAttribute(proj_out,  cudaFuncAttributeMaxDynamicSharedMemorySize, PROJ_SMEM);
    cudaFuncSetAttribute(scores_tc, cudaFuncAttributeMaxDynamicSharedMemorySize, SCORES_SMEM);
    cudaFuncSetAttribute(pv_tc,     cudaFuncAttributeMaxDynamicSharedMemorySize, PV_SMEM);

    ProjArgs pa;
    pa.Ah[0] = pAh;          pa.Al[0] = pAl;          pa.Wh[0] = pWh;          pa.Wl[0] = pWl;
    pa.bias[0] = bq; pa.Ch[0] = pQh; pa.Cl[0] = pQl; pa.Cf[0] = 0; pa.M[0] = NM; pa.split[0] = 1;
    pa.Ah[1] = pAh + AW;     pa.Al[1] = pAl + AW;     pa.Wh[1] = pWh + WW;     pa.Wl[1] = pWl + WW;
    pa.bias[1] = bk; pa.Ch[1] = pKh; pa.Cl[1] = pKl; pa.Cf[1] = 0; pa.M[1] = NM; pa.split[1] = 1;
    pa.Ah[2] = pAh + 2 * AW; pa.Al[2] = pAl + 2 * AW; pa.Wh[2] = pWh + 2 * WW; pa.Wl[2] = pWl + 2 * WW;
    pa.bias[2] = bv; pa.Ch[2] = 0; pa.Cl[2] = 0; pa.Cf[2] = pV; pa.M[2] = NM; pa.split[2] = 0;
    pa.Ah[3] = pPEh;         pa.Al[3] = pPEl;         pa.Wh[3] = pWh + 3 * WW; pa.Wl[3] = pWl + 3 * WW;
    pa.bias[3] = bp; pa.Ch[3] = pEh; pa.Cl[3] = pEl; pa.Cf[3] = 0; pa.M[3] = NR; pa.split[3] = 1;

    pe_kernel<<<NR, 256>>>();
    presplit<<<(3 * AW + 5 * WW + 255) / 256, 256>>>(query, key_, value, Wq, Wk, Wv, Wp, Wo);
    proj_all<<<896, 256, PROJ_SMEM>>>(pa);
    vt_kernel<<<dim3(16, 32), 256>>>();
    ukve_kernel<<<6143, 256>>>(ub, vb);
    scores_tc<<<dim3(8, 16, 32), 256, SCORES_SMEM>>>();
    reduce_kernel<<<128, 256>>>();
    pv_tc<<<dim3(16, 32), 128, PV_SMEM>>>();
    proj_out<<<dim3(8, 32), 256, PROJ_SMEM>>>(pOh, pOl, pWh + 4 * WW, pWl + 4 * WW, bo, out, NM);
}

// round 15
// speedup vs baseline: 1.2610x; 1.0377x over previous
#include <cuda_runtime.h>
#include <cuda_bf16.h>
#include <math.h>

// Problem shapes (fixed by the dataset)
#define NB 4
#define NT 1024
#define ND 512
#define NH 8
#define NDH 64
#define NR 2047          // 2*T - 1
#define NM 4096          // B*T
#define NROWS (NB * NH * NT)   // 32768 score rows
#define NKT 8                  // k-tiles of 128 per row
#define NW 256                 // words per row (512 floats / 2)
#define AW (NM * NW)           // words per split input tensor
#define WW (ND * NW)           // words per split weight matrix

#define PW 36            // padded word-row length (32 data words + 4)
#define GSW 196          // Gs row stride (191 cols + pad)

// ---------------- device scratch (no allocations allowed) ----------------
__device__ unsigned gAh[3 * AW];      // split inputs: query, key, value
__device__ unsigned gAl[3 * AW];
__device__ unsigned gWh[5 * WW];      // split weights: Wq, Wk, Wv, Wp, Wo
__device__ unsigned gWl[5 * WW];
__device__ unsigned gPEh[NR * NW];    // split positional encoding
__device__ unsigned gPEl[NR * NW];
__device__ unsigned gQh[NM * NW];
__device__ unsigned gQl[NM * NW];
__device__ unsigned gKh[NM * NW];
__device__ unsigned gKl[NM * NW];
__device__ unsigned gEh[NR * NW];
__device__ unsigned gEl[NR * NW];
__device__ float    gV[NM * ND];
__device__ unsigned gVth[NB * NH * 64 * 512];   // split V^T [bh][d][posword]
__device__ unsigned gVtl[NB * NH * 64 * 512];
__device__ unsigned gSh[(size_t)NROWS * 512];   // split exp(s - m_tile)
__device__ unsigned gSl[(size_t)NROWS * 512];
__device__ unsigned gOh[NM * NW];     // split attention output
__device__ unsigned gOl[NM * NW];
__device__ float gUK[NB * NH * NT];
__device__ float gVE[NH * NR];
__device__ float gPartM[NROWS * NKT];
__device__ float gPartL[NROWS * NKT];
__device__ float gScale[NROWS * NKT];

// ---------------- bf16 split helpers ----------------
__device__ __forceinline__ void cvt_pair2(float a, float b, unsigned& hi, unsigned& lo) {
    unsigned ha = __bfloat16_as_ushort(__float2bfloat16(a));
    unsigned hb = __bfloat16_as_ushort(__float2bfloat16(b));
    float ra = a - __bfloat162float(__ushort_as_bfloat16((unsigned short)ha));
    float rb = b - __bfloat162float(__ushort_as_bfloat16((unsigned short)hb));
    unsigned la = __bfloat16_as_ushort(__float2bfloat16(ra));
    unsigned lb = __bfloat16_as_ushort(__float2bfloat16(rb));
    hi = (hb << 16) | ha;
    lo = (lb << 16) | la;
}
__device__ __forceinline__ float2 unpack2(unsigned w) {
    return make_float2(__bfloat162float(__ushort_as_bfloat16((unsigned short)(w & 0xffff))),
                       __bfloat162float(__ushort_as_bfloat16((unsigned short)(w >> 16))));
}
__device__ __forceinline__ void mma16(float (&c)[4], unsigned a0, unsigned a1,
                                      unsigned a2, unsigned a3, unsigned b0, unsigned b1) {
    asm volatile(
        "mma.sync.aligned.m16n8k16.row.col.f32.bf16.bf16.f32 "
        "{%0,%1,%2,%3},{%4,%5,%6,%7},{%8,%9},{%0,%1,%2,%3};"
        : "+f"(c[0]), "+f"(c[1]), "+f"(c[2]), "+f"(c[3])
        : "r"(a0), "r"(a1), "r"(a2), "r"(a3), "r"(b0), "r"(b1));
}
__device__ __forceinline__ unsigned smaddr(const void* p) {
    return (unsigned)__cvta_generic_to_shared(p);
}
__device__ __forceinline__ void ldsm4(unsigned& r0, unsigned& r1, unsigned& r2,
                                      unsigned& r3, unsigned a) {
    asm volatile("ldmatrix.sync.aligned.m8n8.x4.shared.b16 {%0,%1,%2,%3}, [%4];"
                 : "=r"(r0), "=r"(r1), "=r"(r2), "=r"(r3) : "r"(a));
}
__device__ __forceinline__ void cpa16(unsigned s, const void* g) {
    asm volatile("cp.async.cg.shared.global [%0], [%1], 16;" :: "r"(s), "l"(g));
}
__device__ __forceinline__ void cpa16p(unsigned s, const void* g, int valid) {
    int sz = valid ? 16 : 0;
    asm volatile("cp.async.cg.shared.global [%0], [%1], 16, %2;"
                 :: "r"(s), "l"(g), "r"(sz));
}
__device__ __forceinline__ void cpa_commit() {
    asm volatile("cp.async.commit_group;" ::: "memory");
}
__device__ __forceinline__ void cpa_wait1() {
    asm volatile("cp.async.wait_group 1;" ::: "memory");
}
__device__ __forceinline__ void cpa_wait0() {
    asm volatile("cp.async.wait_group 0;" ::: "memory");
}
#define AOFF(lane) (((((lane) & 15) * PW + ((lane) >> 4) * 4)) << 2)
#define BOFF(lane) (((((((lane) >> 4) << 3) + ((lane) & 7)) * PW + (((lane) >> 3) & 1) * 4)) << 2)

// ---------------- fused: positional encoding + pre-split inputs/weights ---
__global__ void pe_presplit(const float* __restrict__ q, const float* __restrict__ k,
                            const float* __restrict__ v, const float* __restrict__ wq,
                            const float* __restrict__ wk, const float* __restrict__ wv,
                            const float* __restrict__ wp, const float* __restrict__ wo) {
    int idx = blockIdx.x * 256 + threadIdx.x;
    if (idx < NR * 256) {
        int r = idx >> 8;
        int m = idx & 255;
        float inv = exp2f(-(float)m * (13.287712379549449f / 256.0f));
        float ang = (float)(1023 - r) * inv;
        float s, c;
        sincosf(ang, &s, &c);
        unsigned h, l;
        cvt_pair2(s, c, h, l);
        gPEh[r * NW + m] = h;
        gPEl[r * NW + m] = l;
        return;
    }
    int idx2 = idx - NR * 256;
    if (idx2 < 3 * AW) {
        int z = idx2 / AW, rem = idx2 - z * AW;
        const float* src = (z == 0) ? q : (z == 1) ? k : v;
        cvt_pair2(src[2 * rem], src[2 * rem + 1], gAh[idx2], gAl[idx2]);
    } else {
        int j = idx2 - 3 * AW;
        if (j >= 5 * WW) return;
        int z = j / WW, rem = j - z * WW;
        const float* src = (z == 0) ? wq : (z == 1) ? wk : (z == 2) ? wv
                         : (z == 3) ? wp : wo;
        cvt_pair2(src[2 * rem], src[2 * rem + 1], gWh[j], gWl[j]);
    }
}

// ---------------- GEMM body (pre-split operands, cp.async double-buffer) --
struct ProjArgs {
    const unsigned* Ah[4];
    const unsigned* Al[4];
    const unsigned* Wh[4];
    const unsigned* Wl[4];
    const float*    bias[4];
    unsigned*       Ch[4];
    unsigned*       Cl[4];
    float*          Cf[4];
    int             M[4];
    int             split[4];
};

#define PROJ_BUFW ((2 * 128 + 2 * 64) * PW)   // words per double-buffer stage

__device__ __forceinline__ void proj_issue(const unsigned* __restrict__ Agh,
                                           const unsigned* __restrict__ Agl,
                                           const unsigned* __restrict__ Wgh,
                                           const unsigned* __restrict__ Wgl,
                                           int M, int bm, int bn, int tid,
                                           unsigned uS, int c, int bi) {
    int k0w = c * 32;
    unsigned aH = uS + bi * PROJ_BUFW * 4;
    unsigned aL = aH + 128 * PW * 4;
    unsigned wH = aL + 128 * PW * 4;
    unsigned wL = wH + 64 * PW * 4;
    #pragma unroll
    for (int i = 0; i < 4; i++) {
        int idx = tid + i * 256;
        int row = idx >> 3, w4 = (idx & 7) << 2;
        int grow = bm + row;
        int valid = (grow < M);
        size_t gb = valid ? ((size_t)grow * NW + k0w + w4) : 0;
        cpa16p(aH + (row * PW + w4) * 4, &Agh[gb], valid);
        cpa16p(aL + (row * PW + w4) * 4, &Agl[gb], valid);
    }
    #pragma unroll
    for (int i = 0; i < 2; i++) {
        int idx = tid + i * 256;
        int row = idx >> 3, w4 = (idx & 7) << 2;
        size_t gb = (size_t)(bn + row) * NW + k0w + w4;
        cpa16(wH + (row * PW + w4) * 4, &Wgh[gb]);
        cpa16(wL + (row * PW + w4) * 4, &Wgl[gb]);
    }
    cpa_commit();
}

__device__ __forceinline__ void proj_body(const unsigned* __restrict__ Agh,
                                          const unsigned* __restrict__ Agl,
                                          const unsigned* __restrict__ Wgh,
                                          const unsigned* __restrict__ Wgl,
                                          const float* __restrict__ bias,
                                          unsigned* Ch, unsigned* Cl, float* Cf,
                                          int M, int do_split,
                                          int bx, int by, unsigned* sm) {
    int tid = threadIdx.x;
    int warp = tid >> 5, lane = tid & 31;
    int wm = warp >> 1, wn = warp & 1;
    int g = lane >> 2, t = lane & 3;
    int bm = by * 128, bn = bx * 64;
    float acc[2][4][4] = {};
    unsigned uS = smaddr(sm);
    unsigned aoff = AOFF(lane), boff = BOFF(lane);

    proj_issue(Agh, Agl, Wgh, Wgl, M, bm, bn, tid, uS, 0, 0);
    for (int c = 0; c < 8; c++) {
        int bi = c & 1;
        if (c < 7) {
            proj_issue(Agh, Agl, Wgh, Wgl, M, bm, bn, tid, uS, c + 1, bi ^ 1);
            cpa_wait1();
        } else {
            cpa_wait0();
        }
        __syncthreads();
        unsigned uAh = uS + bi * PROJ_BUFW * 4;
        unsigned uAl = uAh + 128 * PW * 4;
        unsigned uWh = uAl + 128 * PW * 4;
        unsigned uWl = uWh + 64 * PW * 4;
        #pragma unroll
        for (int kw = 0; kw < 32; kw += 8) {
            unsigned ah[2][4], al[2][4];
            #pragma unroll
            for (int mt = 0; mt < 2; mt++) {
                unsigned base = (((wm * 32 + mt * 16) * PW + kw) << 2) + aoff;
                ldsm4(ah[mt][0], ah[mt][1], ah[mt][2], ah[mt][3], uAh + base);
                ldsm4(al[mt][0], al[mt][1], al[mt][2], al[mt][3], uAl + base);
            }
            #pragma unroll
            for (int pair = 0; pair < 2; pair++) {
                unsigned base = (((wn * 32 + pair * 16) * PW + kw) << 2) + boff;
                unsigned bh[4], bl[4];
                ldsm4(bh[0], bh[1], bh[2], bh[3], uWh + base);
                ldsm4(bl[0], bl[1], bl[2], bl[3], uWl + base);
                #pragma unroll
                for (int half = 0; half < 2; half++) {
                    int nt = pair * 2 + half;
                    unsigned bh0 = bh[half * 2], bh1 = bh[half * 2 + 1];
                    unsigned bl0 = bl[half * 2], bl1 = bl[half * 2 + 1];
                    #pragma unroll
                    for (int mt = 0; mt < 2; mt++) {
                        mma16(acc[mt][nt], ah[mt][0], ah[mt][1], ah[mt][2], ah[mt][3], bh0, bh1);
                        mma16(acc[mt][nt], ah[mt][0], ah[mt][1], ah[mt][2], ah[mt][3], bl0, bl1);
                        mma16(acc[mt][nt], al[mt][0], al[mt][1], al[mt][2], al[mt][3], bh0, bh1);
                    }
                }
            }
        }
        __syncthreads();
    }
    #pragma unroll
    for (int mt = 0; mt < 2; mt++) {
        #pragma unroll
        for (int nt = 0; nt < 4; nt++) {
            int row = bm + wm * 32 + mt * 16 + g;
            int col = bn + wn * 32 + nt * 8 + t * 2;
            float f0 = acc[mt][nt][0] + bias[col];
            float f1 = acc[mt][nt][1] + bias[col + 1];
            float f2 = acc[mt][nt][2] + bias[col];
            float f3 = acc[mt][nt][3] + bias[col + 1];
            if (do_split) {
                unsigned h0, l0;
                if (row < M) {
                    cvt_pair2(f0, f1, h0, l0);
                    Ch[(size_t)row * NW + (col >> 1)] = h0;
                    Cl[(size_t)row * NW + (col >> 1)] = l0;
                }
                if (row + 8 < M) {
                    cvt_pair2(f2, f3, h0, l0);
                    Ch[(size_t)(row + 8) * NW + (col >> 1)] = h0;
                    Cl[(size_t)(row + 8) * NW + (col >> 1)] = l0;
                }
            } else {
                if (row < M) {
                    Cf[(size_t)row * 512 + col]     = f0;
                    Cf[(size_t)row * 512 + col + 1] = f1;
                }
                if (row + 8 < M) {
                    Cf[(size_t)(row + 8) * 512 + col]     = f2;
                    Cf[(size_t)(row + 8) * 512 + col + 1] = f3;
                }
            }
        }
    }
}

__global__ void proj_all(ProjArgs a) {
    extern __shared__ unsigned sm[];
    int bid = blockIdx.x;
    int z, bx, by;
    if (bid < 768) { z = bid >> 8; int r = bid & 255; by = r >> 3; bx = r & 7; }
    else           { z = 3;        int r = bid - 768; by = r >> 3; bx = r & 7; }
    proj_body(a.Ah[z], a.Al[z], a.Wh[z], a.Wl[z], a.bias[z],
              a.Ch[z], a.Cl[z], a.Cf[z], a.M[z], a.split[z], bx, by, sm);
}

__global__ void proj_out(const unsigned* __restrict__ Ah, const unsigned* __restrict__ Al,
                         const unsigned* __restrict__ Wh, const unsigned* __restrict__ Wl,
                         const float* __restrict__ bias, float* __restrict__ C, int M) {
    extern __shared__ unsigned sm[];
    proj_body(Ah, Al, Wh, Wl, bias, 0, 0, C, M, 0, blockIdx.x, blockIdx.y, sm);
}

// ---------------- fused: V transpose/split + uK/vE tables ----------------
__global__ void vtukve(const float* __restrict__ u, const float* __restrict__ v) {
    __shared__ float Vs[64][65];
    if (blockIdx.x < 512) {
        int blk = blockIdx.x;
        int bh = blk >> 4, b = bh >> 3, h = bh & 7;
        int p0 = (blk & 15) << 6;
        int tid = threadIdx.x;
        #pragma unroll
        for (int i = 0; i < 16; i++) {
            int idx = tid + i * 256;
            int p = idx >> 6, d = idx & 63;
            Vs[p][d] = gV[(size_t)(b * NT + p0 + p) * ND + h * NDH + d];
        }
        __syncthreads();
        #pragma unroll
        for (int i = 0; i < 8; i++) {
            int idx = tid + i * 256;
            int d = idx >> 5, j = idx & 31;
            unsigned hv, lv;
            cvt_pair2(Vs[2 * j][d], Vs[2 * j + 1][d], hv, lv);
            gVth[(size_t)(bh * 64 + d) * 512 + (p0 >> 1) + j] = hv;
            gVtl[(size_t)(bh * 64 + d) * 512 + (p0 >> 1) + j] = lv;
        }
        return;
    }
    int gid = (blockIdx.x - 512) * 256 + threadIdx.x;
    int w = gid >> 5, lane = gid & 31;
    if (w < NB * NH * NT) {
        int t = w & (NT - 1);
        int bh = w >> 10;
        int h = bh & 7, b = bh >> 3;
        size_t base = (size_t)(b * NT + t) * NW + h * 32 + lane;
        float2 kh = unpack2(gKh[base]);
        float2 kl = unpack2(gKl[base]);
        const float* up = u + h * NDH;
        float s = (kh.x + kl.x) * up[2 * lane] + (kh.y + kl.y) * up[2 * lane + 1];
        #pragma unroll
        for (int o = 16; o; o >>= 1) s += __shfl_down_sync(0xffffffffu, s, o);
        if (lane == 0) gUK[bh * NT + t] = s;
    } else {
        int w2 = w - NB * NH * NT;
        if (w2 >= NH * NR) return;
        int h = w2 / NR;
        int r = w2 - h * NR;
        size_t base = (size_t)r * NW + h * 32 + lane;
        float2 eh = unpack2(gEh[base]);
        float2 el = unpack2(gEl[base]);
        const float* vp = v + h * NDH;
        float s = (eh.x + el.x) * vp[2 * lane] + (eh.y + el.y) * vp[2 * lane + 1];
        #pragma unroll
        for (int o = 16; o; o >>= 1) s += __shfl_down_sync(0xffffffffu, s, o);
        if (lane == 0) gVE[h * NR + r] = s;
    }
}

// ---------------- scores: fused single-pass, split P output ---------------
__global__ void __launch_bounds__(256, 2) scores_tc() {
    extern __shared__ unsigned sm[];
    unsigned* Qh  = sm;                     // 64*PW
    unsigned* Ql  = Qh  + 64 * PW;
    unsigned* Kh  = Ql  + 64 * PW;          // 128*PW
    unsigned* Kl  = Kh  + 128 * PW;
    unsigned* E0h = Kl  + 128 * PW;         // 128*PW
    unsigned* E0l = E0h + 128 * PW;
    unsigned* E1h = E0l + 128 * PW;         // 64*PW
    unsigned* E1l = E1h + 64 * PW;
    float* Gs   = (float*)Kh;               // ALIAS over K/E0 area
    float* redM = (float*)(E1l + 64 * PW);  // [4][64]
    float* redL = redM + 256;               // [4][64]
    int tid = threadIdx.x;
    int bh = blockIdx.z, h = bh & 7, b = bh >> 3;
    int q0 = blockIdx.y * 64, k0 = blockIdx.x * 128;
    int warp = tid >> 5, lane = tid & 31;
    int wm = warp >> 2, wn = warp & 3;
    int g = lane >> 2, t = lane & 3;
    unsigned uQh = smaddr(Qh), uQl = smaddr(Ql);
    unsigned uKh = smaddr(Kh), uKl = smaddr(Kl);
    unsigned uE0h = smaddr(E0h), uE0l = smaddr(E0l);
    unsigned uE1h = smaddr(E1h), uE1l = smaddr(E1l);
    unsigned aoff = AOFF(lane), boff = BOFF(lane);
    int rbase = 960 + k0 - q0;
    const uint4 zero4 = make_uint4(0, 0, 0, 0);

    #pragma unroll
    for (int i = 0; i < 2; i++) {
        int idx = tid + i * 256;
        int row = idx >> 3, w4 = (idx & 7) << 2;
        size_t gbase = (size_t)(b * NT + q0 + row) * NW + h * 32 + w4;
        *(uint4*)&Qh[row * PW + w4] = *(const uint4*)&gQh[gbase];
        *(uint4*)&Ql[row * PW + w4] = *(const uint4*)&gQl[gbase];
    }
    #pragma unroll
    for (int i = 0; i < 4; i++) {
        int idx = tid + i * 256;
        int row = idx >> 3, w4 = (idx & 7) << 2;
        size_t gbase = (size_t)(b * NT + k0 + row) * NW + h * 32 + w4;
        *(uint4*)&Kh[row * PW + w4] = *(const uint4*)&gKh[gbase];
        *(uint4*)&Kl[row * PW + w4] = *(const uint4*)&gKl[gbase];
    }
    #pragma unroll
    for (int i = 0; i < 4; i++) {
        int idx = tid + i * 256;
        int row = idx >> 3, w4 = (idx & 7) << 2;
        int r = rbase + row;
        size_t gbase = (size_t)r * NW + h * 32 + w4;
        *(uint4*)&E0h[row * PW + w4] = (r < NR) ? *(const uint4*)&gEh[gbase] : zero4;
        *(uint4*)&E0l[row * PW + w4] = (r < NR) ? *(const uint4*)&gEl[gbase] : zero4;
    }
    #pragma unroll
    for (int i = 0; i < 2; i++) {
        int idx = tid + i * 256;
        int row = idx >> 3, w4 = (idx & 7) << 2;
        int r = rbase + 128 + row;
        size_t gbase = (size_t)r * NW + h * 32 + w4;
        *(uint4*)&E1h[row * PW + w4] = (r < NR) ? *(const uint4*)&gEh[gbase] : zero4;
        *(uint4*)&E1l[row * PW + w4] = (r < NR) ? *(const uint4*)&gEl[gbase] : zero4;
    }
    __syncthreads();

    float accK[2][4][4] = {};
    float accE[2][4][4] = {};
    float accF[2][2][4] = {};
    #pragma unroll
    for (int kw = 0; kw < 32; kw += 8) {
        unsigned ah[2][4], al[2][4];
        #pragma unroll
        for (int mt = 0; mt < 2; mt++) {
            unsigned base = (((wm * 32 + mt * 16) * PW + kw) << 2) + aoff;
            ldsm4(ah[mt][0], ah[mt][1], ah[mt][2], ah[mt][3], uQh + base);
            ldsm4(al[mt][0], al[mt][1], al[mt][2], al[mt][3], uQl + base);
        }
        #pragma unroll
        for (int pair = 0; pair < 2; pair++) {
            unsigned base = (((wn * 32 + pair * 16) * PW + kw) << 2) + boff;
            unsigned bhv[4], blv[4];
            ldsm4(bhv[0], bhv[1], bhv[2], bhv[3], uKh + base);
            ldsm4(blv[0], blv[1], blv[2], blv[3], uKl + base);
            #pragma unroll
            for (int half = 0; half < 2; half++) {
                int nt = pair * 2 + half;
                #pragma unroll
                for (int mt = 0; mt < 2; mt++) {
                    mma16(accK[mt][nt], ah[mt][0], ah[mt][1], ah[mt][2], ah[mt][3],
                          bhv[half*2], bhv[half*2+1]);
                    mma16(accK[mt][nt], ah[mt][0], ah[mt][1], ah[mt][2], ah[mt][3],
                          blv[half*2], blv[half*2+1]);
                    mma16(accK[mt][nt], al[mt][0], al[mt][1], al[mt][2], al[mt][3],
                          bhv[half*2], bhv[half*2+1]);
                }
            }
        }
        #pragma unroll
        for (int pair = 0; pair < 2; pair++) {
            unsigned base = (((wn * 32 + pair * 16) * PW + kw) << 2) + boff;
            unsigned bhv[4], blv[4];
            ldsm4(bhv[0], bhv[1], bhv[2], bhv[3], uE0h + base);
            ldsm4(blv[0], blv[1], blv[2], blv[3], uE0l + base);
            #pragma unroll
            for (int half = 0; half < 2; half++) {
                int nt = pair * 2 + half;
                #pragma unroll
                for (int mt = 0; mt < 2; mt++) {
                    mma16(accE[mt][nt], ah[mt][0], ah[mt][1], ah[mt][2], ah[mt][3],
                          bhv[half*2], bhv[half*2+1]);
                    mma16(accE[mt][nt], ah[mt][0], ah[mt][1], ah[mt][2], ah[mt][3],
                          blv[half*2], blv[half*2+1]);
                    mma16(accE[mt][nt], al[mt][0], al[mt][1], al[mt][2], al[mt][3],
                          bhv[half*2], bhv[half*2+1]);
                }
            }
        }
        {
            unsigned base = (((wn * 16) * PW + kw) << 2) + boff;
            unsigned bhv[4], blv[4];
            ldsm4(bhv[0], bhv[1], bhv[2], bhv[3], uE1h + base);
            ldsm4(blv[0], blv[1], blv[2], blv[3], uE1l + base);
            #pragma unroll
            for (int half = 0; half < 2; half++) {
                #pragma unroll
                for (int mt = 0; mt < 2; mt++) {
                    mma16(accF[mt][half], ah[mt][0], ah[mt][1], ah[mt][2], ah[mt][3],
                          bhv[half*2], bhv[half*2+1]);
                    mma16(accF[mt][half], ah[mt][0], ah[mt][1], ah[mt][2], ah[mt][3],
                          blv[half*2], blv[half*2+1]);
                    mma16(accF[mt][half], al[mt][0], al[mt][1], al[mt][2], al[mt][3],
                          bhv[half*2], bhv[half*2+1]);
                }
            }
        }
    }
    __syncthreads();

    #pragma unroll
    for (int mt = 0; mt < 2; mt++)
        #pragma unroll
        for (int nt = 0; nt < 4; nt++) {
            int row = wm * 32 + mt * 16 + g;
            int col = wn * 32 + nt * 8 + t * 2;
            Gs[row * GSW + col]           = accE[mt][nt][0];
            Gs[row * GSW + col + 1]       = accE[mt][nt][1];
            Gs[(row + 8) * GSW + col]     = accE[mt][nt][2];
            Gs[(row + 8) * GSW + col + 1] = accE[mt][nt][3];
        }
    #pragma unroll
    for (int mt = 0; mt < 2; mt++)
        #pragma unroll
        for (int nt = 0; nt < 2; nt++) {
            int row = wm * 32 + mt * 16 + g;
            int col = 128 + wn * 16 + nt * 8 + t * 2;
            Gs[row * GSW + col]           = accF[mt][nt][0];
            Gs[row * GSW + col + 1]       = accF[mt][nt][1];
            Gs[(row + 8) * GSW + col]     = accF[mt][nt][2];
            Gs[(row + 8) * GSW + col + 1] = accF[mt][nt][3];
        }
    __syncthreads();

    #pragma unroll
    for (int mt = 0; mt < 2; mt++)
        #pragma unroll
        for (int nt = 0; nt < 4; nt++) {
            int kb = wn * 32 + nt * 8 + t * 2;
            #pragma unroll
            for (int r4 = 0; r4 < 4; r4++) {
                int q = wm * 32 + mt * 16 + g + ((r4 >= 2) ? 8 : 0);
                int k = kb + (r4 & 1);
                int c = k + 63 - q;
                accK[mt][nt][r4] = (accK[mt][nt][r4] + Gs[q * GSW + c]
                                    + gUK[bh * NT + k0 + k] + gVE[h * NR + rbase + c]) * 0.125f;
            }
        }

    float mrow[2][2];
    #pragma unroll
    for (int mt = 0; mt < 2; mt++) {
        mrow[mt][0] = -1e30f; mrow[mt][1] = -1e30f;
        #pragma unroll
        for (int nt = 0; nt < 4; nt++) {
            mrow[mt][0] = fmaxf(mrow[mt][0], fmaxf(accK[mt][nt][0], accK[mt][nt][1]));
            mrow[mt][1] = fmaxf(mrow[mt][1], fmaxf(accK[mt][nt][2], accK[mt][nt][3]));
        }
        #pragma unroll
        for (int hf = 0; hf < 2; hf++) {
            mrow[mt][hf] = fmaxf(mrow[mt][hf], __shfl_xor_sync(0xffffffffu, mrow[mt][hf], 1));
            mrow[mt][hf] = fmaxf(mrow[mt][hf], __shfl_xor_sync(0xffffffffu, mrow[mt][hf], 2));
        }
    }
    if (t == 0) {
        #pragma unroll
        for (int mt = 0; mt < 2; mt++)
            #pragma unroll
            for (int hf = 0; hf < 2; hf++)
                redM[wn * 64 + wm * 32 + mt * 16 + g + hf * 8] = mrow[mt][hf];
    }
    __syncthreads();
    #pragma unroll
    for (int mt = 0; mt < 2; mt++)
        #pragma unroll
        for (int hf = 0; hf < 2; hf++) {
            int row = wm * 32 + mt * 16 + g + hf * 8;
            mrow[mt][hf] = fmaxf(fmaxf(redM[row], redM[64 + row]),
                                 fmaxf(redM[128 + row], redM[192 + row]));
        }

    float srow[2][2] = {};
    #pragma unroll
    for (int mt = 0; mt < 2; mt++)
        #pragma unroll
        for (int nt = 0; nt < 4; nt++) {
            accK[mt][nt][0] = __expf(accK[mt][nt][0] - mrow[mt][0]);
            accK[mt][nt][1] = __expf(accK[mt][nt][1] - mrow[mt][0]);
            accK[mt][nt][2] = __expf(accK[mt][nt][2] - mrow[mt][1]);
            accK[mt][nt][3] = __expf(accK[mt][nt][3] - mrow[mt][1]);
            srow[mt][0] += accK[mt][nt][0] + accK[mt][nt][1];
            srow[mt][1] += accK[mt][nt][2] + accK[mt][nt][3];
        }
    #pragma unroll
    for (int mt = 0; mt < 2; mt++)
        #pragma unroll
        for (int hf = 0; hf < 2; hf++) {
            srow[mt][hf] += __shfl_xor_sync(0xffffffffu, srow[mt][hf], 1);
            srow[mt][hf] += __shfl_xor_sync(0xffffffffu, srow[mt][hf], 2);
        }
    if (t == 0) {
        #pragma unroll
        for (int mt = 0; mt < 2; mt++)
            #pragma unroll
            for (int hf = 0; hf < 2; hf++)
                redL[wn * 64 + wm * 32 + mt * 16 + g + hf * 8] = srow[mt][hf];
    }
    __syncthreads();
    if (wn == 0 && t == 0) {
        #pragma unroll
        for (int mt = 0; mt < 2; mt++)
            #pragma unroll
            for (int hf = 0; hf < 2; hf++) {
                int row = wm * 32 + mt * 16 + g + hf * 8;
                size_t ri = (size_t)(bh * NT + q0 + row) * NKT + blockIdx.x;
                gPartM[ri] = mrow[mt][hf];
                gPartL[ri] = redL[row] + redL[64 + row] + redL[128 + row] + redL[192 + row];
            }
    }

    // ---- store SPLIT exp values ----
    #pragma unroll
    for (int mt = 0; mt < 2; mt++)
        #pragma unroll
        for (int nt = 0; nt < 4; nt++) {
            int kb = wn * 32 + nt * 8 + t * 2;
            int row0 = wm * 32 + mt * 16 + g;
            unsigned h0, l0;
            cvt_pair2(accK[mt][nt][0], accK[mt][nt][1], h0, l0);
            size_t w0 = (size_t)(bh * NT + q0 + row0) * 512 + ((k0 + kb) >> 1);
            gSh[w0] = h0; gSl[w0] = l0;
            cvt_pair2(accK[mt][nt][2], accK[mt][nt][3], h0, l0);
            size_t w1 = (size_t)(bh * NT + q0 + row0 + 8) * 512 + ((k0 + kb) >> 1);
            gSh[w1] = h0; gSl[w1] = l0;
        }
}

// ---------------- combine per-tile stats -> per-(row,tile) scales --------
__global__ void reduce_kernel() {
    int row = blockIdx.x * 256 + threadIdx.x;
    if (row >= NROWS) return;
    size_t base = (size_t)row * NKT;
    float m = -1e30f;
    float pm[NKT], pl[NKT];
    #pragma unroll
    for (int i = 0; i < NKT; i++) {
        pm[i] = gPartM[base + i];
        pl[i] = gPartL[base + i];
        m = fmaxf(m, pm[i]);
    }
    float l = 0.f;
    #pragma unroll
    for (int i = 0; i < NKT; i++) l += __expf(pm[i] - m) * pl[i];
    float inv = 1.f / l;
    #pragma unroll
    for (int i = 0; i < NKT; i++) gScale[base + i] = __expf(pm[i] - m) * inv;
}

// ---------------- O = P @ V: cp.async double-buffer -----------------------
#define PV_BUFW ((4 * 64) * PW)

__device__ __forceinline__ void pv_issue(int bh, int q0, int tid, unsigned uS,
                                         int c, int bi) {
    int kk0w = c * 32;
    unsigned pH = uS + bi * PV_BUFW * 4;
    unsigned pL = pH + 64 * PW * 4;
    unsigned vH = pL + 64 * PW * 4;
    unsigned vL = vH + 64 * PW * 4;
    #pragma unroll
    for (int i = 0; i < 4; i++) {
        int idx = tid + i * 128;
        int row = idx >> 3, w4 = (idx & 7) << 2;
        size_t pb = (size_t)(bh * NT + q0 + row) * 512 + kk0w + w4;
        cpa16(pH + (row * PW + w4) * 4, &gSh[pb]);
        cpa16(pL + (row * PW + w4) * 4, &gSl[pb]);
    }
    #pragma unroll
    for (int i = 0; i < 4; i++) {
        int idx = tid + i * 128;
        int row = idx >> 3, w4 = (idx & 7) << 2;
        size_t vb = (size_t)(bh * 64 + row) * 512 + kk0w + w4;
        cpa16(vH + (row * PW + w4) * 4, &gVth[vb]);
        cpa16(vL + (row * PW + w4) * 4, &gVtl[vb]);
    }
    cpa_commit();
}

__global__ void pv_tc() {
    extern __shared__ unsigned sm[];
    int tid = threadIdx.x;
    int warp = tid >> 5, lane = tid & 31;
    int wm = warp >> 1, wn = warp & 1;
    int g = lane >> 2, t = lane & 3;
    int bh = blockIdx.y, b = bh >> 3;
    int q0 = blockIdx.x * 64;
    float acc[2][4][4] = {};
    unsigned uS = smaddr(sm);
    unsigned aoff = AOFF(lane), boff = BOFF(lane);

    pv_issue(bh, q0, tid, uS, 0, 0);
    for (int c = 0; c < 16; c++) {
        int bi = c & 1;
        int kt = c >> 1;   // NKT tile index: 2 chunks (64 pos each) per 128-pos tile
        if (c < 15) {
            pv_issue(bh, q0, tid, uS, c + 1, bi ^ 1);
            cpa_wait1();
        } else {
            cpa_wait0();
        }
        __syncthreads();
        unsigned uPh = uS + bi * PV_BUFW * 4;
        unsigned uPl = uPh + 64 * PW * 4;
        unsigned uVh = uPl + 64 * PW * 4;
        unsigned uVl = uVh + 64 * PW * 4;
        float ta[2][4][4] = {};
        #pragma unroll
        for (int kw = 0; kw < 32; kw += 8) {
            unsigned ah[2][4], al[2][4];
            #pragma unroll
            for (int mt = 0; mt < 2; mt++) {
                unsigned base = (((wm * 32 + mt * 16) * PW + kw) << 2) + aoff;
                ldsm4(ah[mt][0], ah[mt][1], ah[mt][2], ah[mt][3], uPh + base);
                ldsm4(al[mt][0], al[mt][1], al[mt][2], al[mt][3], uPl + base);
            }
            #pragma unroll
            for (int pair = 0; pair < 2; pair++) {
                unsigned base = (((wn * 32 + pair * 16) * PW + kw) << 2) + boff;
                unsigned bhv[4], blv[4];
                ldsm4(bhv[0], bhv[1], bhv[2], bhv[3], uVh + base);
                ldsm4(blv[0], blv[1], blv[2], blv[3], uVl + base);
                #pragma unroll
                for (int half = 0; half < 2; half++) {
                    int nt = pair * 2 + half;
                    #pragma unroll
                    for (int mt = 0; mt < 2; mt++) {
                        mma16(ta[mt][nt], ah[mt][0], ah[mt][1], ah[mt][2], ah[mt][3],
                              bhv[half*2], bhv[half*2+1]);
                        mma16(ta[mt][nt], ah[mt][0], ah[mt][1], ah[mt][2], ah[mt][3],
                              blv[half*2], blv[half*2+1]);
                        mma16(ta[mt][nt], al[mt][0], al[mt][1], al[mt][2], al[mt][3],
                              bhv[half*2], bhv[half*2+1]);
                    }
                }
            }
        }
        __syncthreads();
        float s0[2], s1[2];
        #pragma unroll
        for (int mt = 0; mt < 2; mt++) {
            s0[mt] = gScale[(size_t)(bh * NT + q0 + wm * 32 + mt * 16 + g) * NKT + kt];
            s1[mt] = gScale[(size_t)(bh * NT + q0 + wm * 32 + mt * 16 + g + 8) * NKT + kt];
        }
        #pragma unroll
        for (int mt = 0; mt < 2; mt++)
            #pragma unroll
            for (int nt = 0; nt < 4; nt++) {
                acc[mt][nt][0] += s0[mt] * ta[mt][nt][0];
                acc[mt][nt][1] += s0[mt] * ta[mt][nt][1];
                acc[mt][nt][2] += s1[mt] * ta[mt][nt][2];
                acc[mt][nt][3] += s1[mt] * ta[mt][nt][3];
            }
    }
    int h = bh & 7;
    #pragma unroll
    for (int mt = 0; mt < 2; mt++)
        #pragma unroll
        for (int nt = 0; nt < 4; nt++) {
            int row = q0 + wm * 32 + mt * 16 + g;
            int col = wn * 32 + nt * 8 + t * 2;
            unsigned hv, lv;
            cvt_pair2(acc[mt][nt][0], acc[mt][nt][1], hv, lv);
            size_t w0 = (size_t)(b * NT + row) * NW + h * 32 + (col >> 1);
            gOh[w0] = hv; gOl[w0] = lv;
            cvt_pair2(acc[mt][nt][2], acc[mt][nt][3], hv, lv);
            size_t w1 = (size_t)(b * NT + row + 8) * NW + h * 32 + (col >> 1);
            gOh[w1] = hv; gOl[w1] = lv;
        }
}

// -------------------------------------------------------------------------
extern "C" void kernel_launch(void* const* d_in, const int* in_sizes, int n_in,
                              void* d_out, int out_size) {
    const float* query = (const float*)d_in[0];
    const float* key_  = (const float*)d_in[1];
    const float* value = (const float*)d_in[2];
    const float* Wq = (const float*)d_in[3];
    const float* bq = (const float*)d_in[4];
    const float* Wk = (const float*)d_in[5];
    const float* bk = (const float*)d_in[6];
    const float* Wv = (const float*)d_in[7];
    const float* bv = (const float*)d_in[8];
    const float* Wp = (const float*)d_in[9];
    const float* bp = (const float*)d_in[10];
    const float* Wo = (const float*)d_in[11];
    const float* bo = (const float*)d_in[12];
    const float* ub = (const float*)d_in[13];
    const float* vb = (const float*)d_in[14];
    float* out = (float*)d_out;

    unsigned *pAh, *pAl, *pWh, *pWl, *pPEh, *pPEl;
    unsigned *pQh, *pQl, *pKh, *pKl, *pEh, *pEl, *pOh, *pOl;
    float *pV;
    cudaGetSymbolAddress((void**)&pAh, gAh);
    cudaGetSymbolAddress((void**)&pAl, gAl);
    cudaGetSymbolAddress((void**)&pWh, gWh);
    cudaGetSymbolAddress((void**)&pWl, gWl);
    cudaGetSymbolAddress((void**)&pPEh, gPEh);
    cudaGetSymbolAddress((void**)&pPEl, gPEl);
    cudaGetSymbolAddress((void**)&pQh, gQh);
    cudaGetSymbolAddress((void**)&pQl, gQl);
    cudaGetSymbolAddress((void**)&pKh, gKh);
    cudaGetSymbolAddress((void**)&pKl, gKl);
    cudaGetSymbolAddress((void**)&pEh, gEh);
    cudaGetSymbolAddress((void**)&pEl, gEl);
    cudaGetSymbolAddress((void**)&pOh, gOh);
    cudaGetSymbolAddress((void**)&pOl, gOl);
    cudaGetSymbolAddress((void**)&pV, gV);

    const int PROJ_SMEM   = 2 * PROJ_BUFW * 4;                                // 110592
    const int SCORES_SMEM = (2 * PW * (64 + 128 + 128 + 64) + 512) * 4;       // 112640
    const int PV_SMEM     = 2 * PV_BUFW * 4;                                  // 73728
    cudaFuncSetAttribute(proj_all,  cudaFuncAttributeMaxDynamicSharedMemorySize, PROJ_SMEM);
    cudaFuncSetAttribute(proj_out,  cudaFuncAttributeMaxDynamicSharedMemorySize, PROJ_SMEM);
    cudaFuncSetAttribute(scores_tc, cudaFuncAttributeMaxDynamicSharedMemorySize, SCORES_SMEM);
    cudaFuncSetAttribute(pv_tc,     cudaFuncAttributeMaxDynamicSharedMemorySize, PV_SMEM);

    ProjArgs pa;
    pa.Ah[0] = pAh;          pa.Al[0] = pAl;          pa.Wh[0] = pWh;          pa.Wl[0] = pWl;
    pa.bias[0] = bq; pa.Ch[0] = pQh; pa.Cl[0] = pQl; pa.Cf[0] = 0; pa.M[0] = NM; pa.split[0] = 1;
    pa.Ah[1] = pAh + AW;     pa.Al[1] = pAl + AW;     pa.Wh[1] = pWh + WW;     pa.Wl[1] = pWl + WW;
    pa.bias[1] = bk; pa.Ch[1] = pKh; pa.Cl[1] = pKl; pa.Cf[1] = 0; pa.M[1] = NM; pa.split[1] = 1;
    pa.Ah[2] = pAh + 2 * AW; pa.Al[2] = pAl + 2 * AW; pa.Wh[2] = pWh + 2 * WW; pa.Wl[2] = pWl + 2 * WW;
    pa.bias[2] = bv; pa.Ch[2] = 0; pa.Cl[2] = 0; pa.Cf[2] = pV; pa.M[2] = NM; pa.split[2] = 0;
    pa.Ah[3] = pPEh;         pa.Al[3] = pPEl;         pa.Wh[3] = pWh + 3 * WW; pa.Wl[3] = pWl + 3 * WW;
    pa.bias[3] = bp; pa.Ch[3] = pEh; pa.Cl[3] = pEl; pa.Cf[3] = 0; pa.M[3] = NR; pa.split[3] = 1;

    pe_presplit<<<(NR * 256 + 3 * AW + 5 * WW + 255) / 256, 256>>>(
        query, key_, value, Wq, Wk, Wv, Wp, Wo);
    proj_all<<<896, 256, PROJ_SMEM>>>(pa);
    vtukve<<<512 + 6143, 256>>>(ub, vb);
    scores_tc<<<dim3(8, 16, 32), 256, SCORES_SMEM>>>();
    reduce_kernel<<<128, 256>>>();
    pv_tc<<<dim3(16, 32), 128, PV_SMEM>>>();
    proj_out<<<dim3(8, 32), 256, PROJ_SMEM>>>(pOh, pOl, pWh + 4 * WW, pWl + 4 * WW, bo, out, NM);
}

// round 16
// speedup vs baseline: 1.3410x; 1.0634x over previous
#include <cuda_runtime.h>
#include <cuda_bf16.h>
#include <math.h>

// Problem shapes (fixed by the dataset)
#define NB 4
#define NT 1024
#define ND 512
#define NH 8
#define NDH 64
#define NR 2047          // 2*T - 1
#define NM 4096          // B*T
#define NROWS (NB * NH * NT)   // 32768 score rows
#define NKT 8                  // k-tiles of 128 per row
#define NW 256                 // words per row (512 floats / 2)
#define AW (NM * NW)           // words per split input tensor
#define WW (ND * NW)           // words per split weight matrix

#define PW 36            // padded word-row length (32 data words + 4)
#define GSW 196          // Gs row stride (191 cols + pad)

// ---------------- device scratch (no allocations allowed) ----------------
__device__ unsigned gAh[3 * AW];      // split inputs: query, key, value
__device__ unsigned gAl[3 * AW];
__device__ unsigned gWh[5 * WW];      // split weights: Wq, Wk, Wv, Wp, Wo
__device__ unsigned gWl[5 * WW];
__device__ unsigned gPEh[NR * NW];    // split positional encoding
__device__ unsigned gPEl[NR * NW];
__device__ unsigned gQh[NM * NW];
__device__ unsigned gQl[NM * NW];
__device__ unsigned gKh[NM * NW];
__device__ unsigned gKl[NM * NW];
__device__ unsigned gEh[NR * NW];
__device__ unsigned gEl[NR * NW];
__device__ float    gV[NM * ND];
__device__ unsigned gVth[NB * NH * 64 * 512];   // split V^T [bh][d][posword]
__device__ unsigned gVtl[NB * NH * 64 * 512];
__device__ unsigned gSh[(size_t)NROWS * 512];   // split exp(s - m_tile)
__device__ unsigned gSl[(size_t)NROWS * 512];
__device__ unsigned gOh[NM * NW];     // split attention output
__device__ unsigned gOl[NM * NW];
__device__ float gUK[NB * NH * NT];
__device__ float gVE[NH * NR];
__device__ float gPartM[NROWS * NKT];
__device__ float gPartL[NROWS * NKT];

// ---------------- bf16 split helpers ----------------
__device__ __forceinline__ void cvt_pair2(float a, float b, unsigned& hi, unsigned& lo) {
    unsigned ha = __bfloat16_as_ushort(__float2bfloat16(a));
    unsigned hb = __bfloat16_as_ushort(__float2bfloat16(b));
    float ra = a - __bfloat162float(__ushort_as_bfloat16((unsigned short)ha));
    float rb = b - __bfloat162float(__ushort_as_bfloat16((unsigned short)hb));
    unsigned la = __bfloat16_as_ushort(__float2bfloat16(ra));
    unsigned lb = __bfloat16_as_ushort(__float2bfloat16(rb));
    hi = (hb << 16) | ha;
    lo = (lb << 16) | la;
}
__device__ __forceinline__ float2 unpack2(unsigned w) {
    return make_float2(__bfloat162float(__ushort_as_bfloat16((unsigned short)(w & 0xffff))),
                       __bfloat162float(__ushort_as_bfloat16((unsigned short)(w >> 16))));
}
__device__ __forceinline__ void mma16(float (&c)[4], unsigned a0, unsigned a1,
                                      unsigned a2, unsigned a3, unsigned b0, unsigned b1) {
    asm volatile(
        "mma.sync.aligned.m16n8k16.row.col.f32.bf16.bf16.f32 "
        "{%0,%1,%2,%3},{%4,%5,%6,%7},{%8,%9},{%0,%1,%2,%3};"
        : "+f"(c[0]), "+f"(c[1]), "+f"(c[2]), "+f"(c[3])
        : "r"(a0), "r"(a1), "r"(a2), "r"(a3), "r"(b0), "r"(b1));
}
__device__ __forceinline__ unsigned smaddr(const void* p) {
    return (unsigned)__cvta_generic_to_shared(p);
}
__device__ __forceinline__ void ldsm4(unsigned& r0, unsigned& r1, unsigned& r2,
                                      unsigned& r3, unsigned a) {
    asm volatile("ldmatrix.sync.aligned.m8n8.x4.shared.b16 {%0,%1,%2,%3}, [%4];"
                 : "=r"(r0), "=r"(r1), "=r"(r2), "=r"(r3) : "r"(a));
}
__device__ __forceinline__ void cpa16(unsigned s, const void* g) {
    asm volatile("cp.async.cg.shared.global [%0], [%1], 16;" :: "r"(s), "l"(g));
}
__device__ __forceinline__ void cpa16p(unsigned s, const void* g, int valid) {
    int sz = valid ? 16 : 0;
    asm volatile("cp.async.cg.shared.global [%0], [%1], 16, %2;"
                 :: "r"(s), "l"(g), "r"(sz));
}
__device__ __forceinline__ void cpa_commit() {
    asm volatile("cp.async.commit_group;" ::: "memory");
}
__device__ __forceinline__ void cpa_wait1() {
    asm volatile("cp.async.wait_group 1;" ::: "memory");
}
__device__ __forceinline__ void cpa_wait0() {
    asm volatile("cp.async.wait_group 0;" ::: "memory");
}
#define AOFF(lane) (((((lane) & 15) * PW + ((lane) >> 4) * 4)) << 2)
#define BOFF(lane) (((((((lane) >> 4) << 3) + ((lane) & 7)) * PW + (((lane) >> 3) & 1) * 4)) << 2)

// ---------------- fused: positional encoding + pre-split inputs/weights ---
__global__ void pe_presplit(const float* __restrict__ q, const float* __restrict__ k,
                            const float* __restrict__ v, const float* __restrict__ wq,
                            const float* __restrict__ wk, const float* __restrict__ wv,
                            const float* __restrict__ wp, const float* __restrict__ wo) {
    int idx = blockIdx.x * 256 + threadIdx.x;
    if (idx < NR * 256) {
        int r = idx >> 8;
        int m = idx & 255;
        float inv = exp2f(-(float)m * (13.287712379549449f / 256.0f));
        float ang = (float)(1023 - r) * inv;
        float s, c;
        sincosf(ang, &s, &c);
        unsigned h, l;
        cvt_pair2(s, c, h, l);
        gPEh[r * NW + m] = h;
        gPEl[r * NW + m] = l;
        return;
    }
    int idx2 = idx - NR * 256;
    if (idx2 < 3 * AW) {
        int z = idx2 / AW, rem = idx2 - z * AW;
        const float* src = (z == 0) ? q : (z == 1) ? k : v;
        cvt_pair2(src[2 * rem], src[2 * rem + 1], gAh[idx2], gAl[idx2]);
    } else {
        int j = idx2 - 3 * AW;
        if (j >= 5 * WW) return;
        int z = j / WW, rem = j - z * WW;
        const float* src = (z == 0) ? wq : (z == 1) ? wk : (z == 2) ? wv
                         : (z == 3) ? wp : wo;
        cvt_pair2(src[2 * rem], src[2 * rem + 1], gWh[j], gWl[j]);
    }
}

// ---------------- GEMM body (pre-split operands, cp.async double-buffer) --
struct ProjArgs {
    const unsigned* Ah[4];
    const unsigned* Al[4];
    const unsigned* Wh[4];
    const unsigned* Wl[4];
    const float*    bias[4];
    unsigned*       Ch[4];
    unsigned*       Cl[4];
    float*          Cf[4];
    int             M[4];
    int             split[4];
};

#define PROJ_BUFW ((2 * 128 + 2 * 64) * PW)   // words per double-buffer stage

__device__ __forceinline__ void proj_issue(const unsigned* __restrict__ Agh,
                                           const unsigned* __restrict__ Agl,
                                           const unsigned* __restrict__ Wgh,
                                           const unsigned* __restrict__ Wgl,
                                           int M, int bm, int bn, int tid,
                                           unsigned uS, int c, int bi) {
    int k0w = c * 32;
    unsigned aH = uS + bi * PROJ_BUFW * 4;
    unsigned aL = aH + 128 * PW * 4;
    unsigned wH = aL + 128 * PW * 4;
    unsigned wL = wH + 64 * PW * 4;
    #pragma unroll
    for (int i = 0; i < 4; i++) {
        int idx = tid + i * 256;
        int row = idx >> 3, w4 = (idx & 7) << 2;
        int grow = bm + row;
        int valid = (grow < M);
        size_t gb = valid ? ((size_t)grow * NW + k0w + w4) : 0;
        cpa16p(aH + (row * PW + w4) * 4, &Agh[gb], valid);
        cpa16p(aL + (row * PW + w4) * 4, &Agl[gb], valid);
    }
    #pragma unroll
    for (int i = 0; i < 2; i++) {
        int idx = tid + i * 256;
        int row = idx >> 3, w4 = (idx & 7) << 2;
        size_t gb = (size_t)(bn + row) * NW + k0w + w4;
        cpa16(wH + (row * PW + w4) * 4, &Wgh[gb]);
        cpa16(wL + (row * PW + w4) * 4, &Wgl[gb]);
    }
    cpa_commit();
}

__device__ __forceinline__ void proj_body(const unsigned* __restrict__ Agh,
                                          const unsigned* __restrict__ Agl,
                                          const unsigned* __restrict__ Wgh,
                                          const unsigned* __restrict__ Wgl,
                                          const float* __restrict__ bias,
                                          unsigned* Ch, unsigned* Cl, float* Cf,
                                          int M, int do_split,
                                          int bx, int by, unsigned* sm) {
    int tid = threadIdx.x;
    int warp = tid >> 5, lane = tid & 31;
    int wm = warp >> 1, wn = warp & 1;
    int g = lane >> 2, t = lane & 3;
    int bm = by * 128, bn = bx * 64;
    float acc[2][4][4] = {};
    unsigned uS = smaddr(sm);
    unsigned aoff = AOFF(lane), boff = BOFF(lane);

    proj_issue(Agh, Agl, Wgh, Wgl, M, bm, bn, tid, uS, 0, 0);
    for (int c = 0; c < 8; c++) {
        int bi = c & 1;
        if (c < 7) {
            proj_issue(Agh, Agl, Wgh, Wgl, M, bm, bn, tid, uS, c + 1, bi ^ 1);
            cpa_wait1();
        } else {
            cpa_wait0();
        }
        __syncthreads();
        unsigned uAh = uS + bi * PROJ_BUFW * 4;
        unsigned uAl = uAh + 128 * PW * 4;
        unsigned uWh = uAl + 128 * PW * 4;
        unsigned uWl = uWh + 64 * PW * 4;
        #pragma unroll
        for (int kw = 0; kw < 32; kw += 8) {
            unsigned ah[2][4], al[2][4];
            #pragma unroll
            for (int mt = 0; mt < 2; mt++) {
                unsigned base = (((wm * 32 + mt * 16) * PW + kw) << 2) + aoff;
                ldsm4(ah[mt][0], ah[mt][1], ah[mt][2], ah[mt][3], uAh + base);
                ldsm4(al[mt][0], al[mt][1], al[mt][2], al[mt][3], uAl + base);
            }
            #pragma unroll
            for (int pair = 0; pair < 2; pair++) {
                unsigned base = (((wn * 32 + pair * 16) * PW + kw) << 2) + boff;
                unsigned bh[4], bl[4];
                ldsm4(bh[0], bh[1], bh[2], bh[3], uWh + base);
                ldsm4(bl[0], bl[1], bl[2], bl[3], uWl + base);
                #pragma unroll
                for (int half = 0; half < 2; half++) {
                    int nt = pair * 2 + half;
                    unsigned bh0 = bh[half * 2], bh1 = bh[half * 2 + 1];
                    unsigned bl0 = bl[half * 2], bl1 = bl[half * 2 + 1];
                    #pragma unroll
                    for (int mt = 0; mt < 2; mt++) {
                        mma16(acc[mt][nt], ah[mt][0], ah[mt][1], ah[mt][2], ah[mt][3], bh0, bh1);
                        mma16(acc[mt][nt], ah[mt][0], ah[mt][1], ah[mt][2], ah[mt][3], bl0, bl1);
                        mma16(acc[mt][nt], al[mt][0], al[mt][1], al[mt][2], al[mt][3], bh0, bh1);
                    }
                }
            }
        }
        __syncthreads();
    }
    #pragma unroll
    for (int mt = 0; mt < 2; mt++) {
        #pragma unroll
        for (int nt = 0; nt < 4; nt++) {
            int row = bm + wm * 32 + mt * 16 + g;
            int col = bn + wn * 32 + nt * 8 + t * 2;
            float f0 = acc[mt][nt][0] + bias[col];
            float f1 = acc[mt][nt][1] + bias[col + 1];
            float f2 = acc[mt][nt][2] + bias[col];
            float f3 = acc[mt][nt][3] + bias[col + 1];
            if (do_split) {
                unsigned h0, l0;
                if (row < M) {
                    cvt_pair2(f0, f1, h0, l0);
                    Ch[(size_t)row * NW + (col >> 1)] = h0;
                    Cl[(size_t)row * NW + (col >> 1)] = l0;
                }
                if (row + 8 < M) {
                    cvt_pair2(f2, f3, h0, l0);
                    Ch[(size_t)(row + 8) * NW + (col >> 1)] = h0;
                    Cl[(size_t)(row + 8) * NW + (col >> 1)] = l0;
                }
            } else {
                if (row < M) {
                    Cf[(size_t)row * 512 + col]     = f0;
                    Cf[(size_t)row * 512 + col + 1] = f1;
                }
                if (row + 8 < M) {
                    Cf[(size_t)(row + 8) * 512 + col]     = f2;
                    Cf[(size_t)(row + 8) * 512 + col + 1] = f3;
                }
            }
        }
    }
}

__global__ void proj_all(ProjArgs a) {
    extern __shared__ unsigned sm[];
    int bid = blockIdx.x;
    int z, bx, by;
    if (bid < 768) { z = bid >> 8; int r = bid & 255; by = r >> 3; bx = r & 7; }
    else           { z = 3;        int r = bid - 768; by = r >> 3; bx = r & 7; }
    proj_body(a.Ah[z], a.Al[z], a.Wh[z], a.Wl[z], a.bias[z],
              a.Ch[z], a.Cl[z], a.Cf[z], a.M[z], a.split[z], bx, by, sm);
}

__global__ void proj_out(const unsigned* __restrict__ Ah, const unsigned* __restrict__ Al,
                         const unsigned* __restrict__ Wh, const unsigned* __restrict__ Wl,
                         const float* __restrict__ bias, float* __restrict__ C, int M) {
    extern __shared__ unsigned sm[];
    proj_body(Ah, Al, Wh, Wl, bias, 0, 0, C, M, 0, blockIdx.x, blockIdx.y, sm);
}

// ---------------- fused: V transpose/split + uK/vE tables ----------------
__global__ void vtukve(const float* __restrict__ u, const float* __restrict__ v) {
    __shared__ float Vs[64][65];
    if (blockIdx.x < 512) {
        int blk = blockIdx.x;
        int bh = blk >> 4, b = bh >> 3, h = bh & 7;
        int p0 = (blk & 15) << 6;
        int tid = threadIdx.x;
        #pragma unroll
        for (int i = 0; i < 16; i++) {
            int idx = tid + i * 256;
            int p = idx >> 6, d = idx & 63;
            Vs[p][d] = gV[(size_t)(b * NT + p0 + p) * ND + h * NDH + d];
        }
        __syncthreads();
        #pragma unroll
        for (int i = 0; i < 8; i++) {
            int idx = tid + i * 256;
            int d = idx >> 5, j = idx & 31;
            unsigned hv, lv;
            cvt_pair2(Vs[2 * j][d], Vs[2 * j + 1][d], hv, lv);
            gVth[(size_t)(bh * 64 + d) * 512 + (p0 >> 1) + j] = hv;
            gVtl[(size_t)(bh * 64 + d) * 512 + (p0 >> 1) + j] = lv;
        }
        return;
    }
    int gid = (blockIdx.x - 512) * 256 + threadIdx.x;
    int w = gid >> 5, lane = gid & 31;
    if (w < NB * NH * NT) {
        int t = w & (NT - 1);
        int bh = w >> 10;
        int h = bh & 7, b = bh >> 3;
        size_t base = (size_t)(b * NT + t) * NW + h * 32 + lane;
        float2 kh = unpack2(gKh[base]);
        float2 kl = unpack2(gKl[base]);
        const float* up = u + h * NDH;
        float s = (kh.x + kl.x) * up[2 * lane] + (kh.y + kl.y) * up[2 * lane + 1];
        #pragma unroll
        for (int o = 16; o; o >>= 1) s += __shfl_down_sync(0xffffffffu, s, o);
        if (lane == 0) gUK[bh * NT + t] = s;
    } else {
        int w2 = w - NB * NH * NT;
        if (w2 >= NH * NR) return;
        int h = w2 / NR;
        int r = w2 - h * NR;
        size_t base = (size_t)r * NW + h * 32 + lane;
        float2 eh = unpack2(gEh[base]);
        float2 el = unpack2(gEl[base]);
        const float* vp = v + h * NDH;
        float s = (eh.x + el.x) * vp[2 * lane] + (eh.y + el.y) * vp[2 * lane + 1];
        #pragma unroll
        for (int o = 16; o; o >>= 1) s += __shfl_down_sync(0xffffffffu, s, o);
        if (lane == 0) gVE[h * NR + r] = s;
    }
}

// ---------------- scores: fused single-pass, cp.async loads ---------------
__global__ void __launch_bounds__(256, 2) scores_tc() {
    extern __shared__ unsigned sm[];
    unsigned* Qh  = sm;                     // 64*PW
    unsigned* Ql  = Qh  + 64 * PW;
    unsigned* Kh  = Ql  + 64 * PW;          // 128*PW
    unsigned* Kl  = Kh  + 128 * PW;
    unsigned* E0h = Kl  + 128 * PW;         // 128*PW
    unsigned* E0l = E0h + 128 * PW;
    unsigned* E1h = E0l + 128 * PW;         // 64*PW
    unsigned* E1l = E1h + 64 * PW;
    float* Gs   = (float*)Kh;               // ALIAS over K/E0 area
    float* redM = (float*)(E1l + 64 * PW);  // [4][64]
    float* redL = redM + 256;               // [4][64]
    int tid = threadIdx.x;
    int bh = blockIdx.z, h = bh & 7, b = bh >> 3;
    int q0 = blockIdx.y * 64, k0 = blockIdx.x * 128;
    int warp = tid >> 5, lane = tid & 31;
    int wm = warp >> 2, wn = warp & 3;
    int g = lane >> 2, t = lane & 3;
    unsigned uQh = smaddr(Qh), uQl = smaddr(Ql);
    unsigned uKh = smaddr(Kh), uKl = smaddr(Kl);
    unsigned uE0h = smaddr(E0h), uE0l = smaddr(E0l);
    unsigned uE1h = smaddr(E1h), uE1l = smaddr(E1l);
    unsigned aoff = AOFF(lane), boff = BOFF(lane);
    int rbase = 960 + k0 - q0;

    // ---- cp.async all tiles: Q(64), K(128), E0(128), E1(64) ----
    #pragma unroll
    for (int i = 0; i < 2; i++) {
        int idx = tid + i * 256;
        int row = idx >> 3, w4 = (idx & 7) << 2;
        size_t gbase = (size_t)(b * NT + q0 + row) * NW + h * 32 + w4;
        cpa16(uQh + (row * PW + w4) * 4, &gQh[gbase]);
        cpa16(uQl + (row * PW + w4) * 4, &gQl[gbase]);
    }
    #pragma unroll
    for (int i = 0; i < 4; i++) {
        int idx = tid + i * 256;
        int row = idx >> 3, w4 = (idx & 7) << 2;
        size_t gbase = (size_t)(b * NT + k0 + row) * NW + h * 32 + w4;
        cpa16(uKh + (row * PW + w4) * 4, &gKh[gbase]);
        cpa16(uKl + (row * PW + w4) * 4, &gKl[gbase]);
    }
    #pragma unroll
    for (int i = 0; i < 4; i++) {
        int idx = tid + i * 256;
        int row = idx >> 3, w4 = (idx & 7) << 2;
        int r = rbase + row;
        int valid = (r < NR);
        size_t gbase = valid ? ((size_t)r * NW + h * 32 + w4) : 0;
        cpa16p(uE0h + (row * PW + w4) * 4, &gEh[gbase], valid);
        cpa16p(uE0l + (row * PW + w4) * 4, &gEl[gbase], valid);
    }
    #pragma unroll
    for (int i = 0; i < 2; i++) {
        int idx = tid + i * 256;
        int row = idx >> 3, w4 = (idx & 7) << 2;
        int r = rbase + 128 + row;
        int valid = (r < NR);
        size_t gbase = valid ? ((size_t)r * NW + h * 32 + w4) : 0;
        cpa16p(uE1h + (row * PW + w4) * 4, &gEh[gbase], valid);
        cpa16p(uE1l + (row * PW + w4) * 4, &gEl[gbase], valid);
    }
    cpa_commit();
    cpa_wait0();
    __syncthreads();

    float accK[2][4][4] = {};
    float accE[2][4][4] = {};
    float accF[2][2][4] = {};
    #pragma unroll
    for (int kw = 0; kw < 32; kw += 8) {
        unsigned ah[2][4], al[2][4];
        #pragma unroll
        for (int mt = 0; mt < 2; mt++) {
            unsigned base = (((wm * 32 + mt * 16) * PW + kw) << 2) + aoff;
            ldsm4(ah[mt][0], ah[mt][1], ah[mt][2], ah[mt][3], uQh + base);
            ldsm4(al[mt][0], al[mt][1], al[mt][2], al[mt][3], uQl + base);
        }
        #pragma unroll
        for (int pair = 0; pair < 2; pair++) {
            unsigned base = (((wn * 32 + pair * 16) * PW + kw) << 2) + boff;
            unsigned bhv[4], blv[4];
            ldsm4(bhv[0], bhv[1], bhv[2], bhv[3], uKh + base);
            ldsm4(blv[0], blv[1], blv[2], blv[3], uKl + base);
            #pragma unroll
            for (int half = 0; half < 2; half++) {
                int nt = pair * 2 + half;
                #pragma unroll
                for (int mt = 0; mt < 2; mt++) {
                    mma16(accK[mt][nt], ah[mt][0], ah[mt][1], ah[mt][2], ah[mt][3],
                          bhv[half*2], bhv[half*2+1]);
                    mma16(accK[mt][nt], ah[mt][0], ah[mt][1], ah[mt][2], ah[mt][3],
                          blv[half*2], blv[half*2+1]);
                    mma16(accK[mt][nt], al[mt][0], al[mt][1], al[mt][2], al[mt][3],
                          bhv[half*2], bhv[half*2+1]);
                }
            }
        }
        #pragma unroll
        for (int pair = 0; pair < 2; pair++) {
            unsigned base = (((wn * 32 + pair * 16) * PW + kw) << 2) + boff;
            unsigned bhv[4], blv[4];
            ldsm4(bhv[0], bhv[1], bhv[2], bhv[3], uE0h + base);
            ldsm4(blv[0], blv[1], blv[2], blv[3], uE0l + base);
            #pragma unroll
            for (int half = 0; half < 2; half++) {
                int nt = pair * 2 + half;
                #pragma unroll
                for (int mt = 0; mt < 2; mt++) {
                    mma16(accE[mt][nt], ah[mt][0], ah[mt][1], ah[mt][2], ah[mt][3],
                          bhv[half*2], bhv[half*2+1]);
                    mma16(accE[mt][nt], ah[mt][0], ah[mt][1], ah[mt][2], ah[mt][3],
                          blv[half*2], blv[half*2+1]);
                    mma16(accE[mt][nt], al[mt][0], al[mt][1], al[mt][2], al[mt][3],
                          bhv[half*2], bhv[half*2+1]);
                }
            }
        }
        {
            unsigned base = (((wn * 16) * PW + kw) << 2) + boff;
            unsigned bhv[4], blv[4];
            ldsm4(bhv[0], bhv[1], bhv[2], bhv[3], uE1h + base);
            ldsm4(blv[0], blv[1], blv[2], blv[3], uE1l + base);
            #pragma unroll
            for (int half = 0; half < 2; half++) {
                #pragma unroll
                for (int mt = 0; mt < 2; mt++) {
                    mma16(accF[mt][half], ah[mt][0], ah[mt][1], ah[mt][2], ah[mt][3],
                          bhv[half*2], bhv[half*2+1]);
                    mma16(accF[mt][half], ah[mt][0], ah[mt][1], ah[mt][2], ah[mt][3],
                          blv[half*2], blv[half*2+1]);
                    mma16(accF[mt][half], al[mt][0], al[mt][1], al[mt][2], al[mt][3],
                          bhv[half*2], bhv[half*2+1]);
                }
            }
        }
    }
    __syncthreads();

    #pragma unroll
    for (int mt = 0; mt < 2; mt++)
        #pragma unroll
        for (int nt = 0; nt < 4; nt++) {
            int row = wm * 32 + mt * 16 + g;
            int col = wn * 32 + nt * 8 + t * 2;
            Gs[row * GSW + col]           = accE[mt][nt][0];
            Gs[row * GSW + col + 1]       = accE[mt][nt][1];
            Gs[(row + 8) * GSW + col]     = accE[mt][nt][2];
            Gs[(row + 8) * GSW + col + 1] = accE[mt][nt][3];
        }
    #pragma unroll
    for (int mt = 0; mt < 2; mt++)
        #pragma unroll
        for (int nt = 0; nt < 2; nt++) {
            int row = wm * 32 + mt * 16 + g;
            int col = 128 + wn * 16 + nt * 8 + t * 2;
            Gs[row * GSW + col]           = accF[mt][nt][0];
            Gs[row * GSW + col + 1]       = accF[mt][nt][1];
            Gs[(row + 8) * GSW + col]     = accF[mt][nt][2];
            Gs[(row + 8) * GSW + col + 1] = accF[mt][nt][3];
        }
    __syncthreads();

    #pragma unroll
    for (int mt = 0; mt < 2; mt++)
        #pragma unroll
        for (int nt = 0; nt < 4; nt++) {
            int kb = wn * 32 + nt * 8 + t * 2;
            #pragma unroll
            for (int r4 = 0; r4 < 4; r4++) {
                int q = wm * 32 + mt * 16 + g + ((r4 >= 2) ? 8 : 0);
                int k = kb + (r4 & 1);
                int c = k + 63 - q;
                accK[mt][nt][r4] = (accK[mt][nt][r4] + Gs[q * GSW + c]
                                    + gUK[bh * NT + k0 + k] + gVE[h * NR + rbase + c]) * 0.125f;
            }
        }

    float mrow[2][2];
    #pragma unroll
    for (int mt = 0; mt < 2; mt++) {
        mrow[mt][0] = -1e30f; mrow[mt][1] = -1e30f;
        #pragma unroll
        for (int nt = 0; nt < 4; nt++) {
            mrow[mt][0] = fmaxf(mrow[mt][0], fmaxf(accK[mt][nt][0], accK[mt][nt][1]));
            mrow[mt][1] = fmaxf(mrow[mt][1], fmaxf(accK[mt][nt][2], accK[mt][nt][3]));
        }
        #pragma unroll
        for (int hf = 0; hf < 2; hf++) {
            mrow[mt][hf] = fmaxf(mrow[mt][hf], __shfl_xor_sync(0xffffffffu, mrow[mt][hf], 1));
            mrow[mt][hf] = fmaxf(mrow[mt][hf], __shfl_xor_sync(0xffffffffu, mrow[mt][hf], 2));
        }
    }
    if (t == 0) {
        #pragma unroll
        for (int mt = 0; mt < 2; mt++)
            #pragma unroll
            for (int hf = 0; hf < 2; hf++)
                redM[wn * 64 + wm * 32 + mt * 16 + g + hf * 8] = mrow[mt][hf];
    }
    __syncthreads();
    #pragma unroll
    for (int mt = 0; mt < 2; mt++)
        #pragma unroll
        for (int hf = 0; hf < 2; hf++) {
            int row = wm * 32 + mt * 16 + g + hf * 8;
            mrow[mt][hf] = fmaxf(fmaxf(redM[row], redM[64 + row]),
                                 fmaxf(redM[128 + row], redM[192 + row]));
        }

    float srow[2][2] = {};
    #pragma unroll
    for (int mt = 0; mt < 2; mt++)
        #pragma unroll
        for (int nt = 0; nt < 4; nt++) {
            accK[mt][nt][0] = __expf(accK[mt][nt][0] - mrow[mt][0]);
            accK[mt][nt][1] = __expf(accK[mt][nt][1] - mrow[mt][0]);
            accK[mt][nt][2] = __expf(accK[mt][nt][2] - mrow[mt][1]);
            accK[mt][nt][3] = __expf(accK[mt][nt][3] - mrow[mt][1]);
            srow[mt][0] += accK[mt][nt][0] + accK[mt][nt][1];
            srow[mt][1] += accK[mt][nt][2] + accK[mt][nt][3];
        }
    #pragma unroll
    for (int mt = 0; mt < 2; mt++)
        #pragma unroll
        for (int hf = 0; hf < 2; hf++) {
            srow[mt][hf] += __shfl_xor_sync(0xffffffffu, srow[mt][hf], 1);
            srow[mt][hf] += __shfl_xor_sync(0xffffffffu, srow[mt][hf], 2);
        }
    if (t == 0) {
        #pragma unroll
        for (int mt = 0; mt < 2; mt++)
            #pragma unroll
            for (int hf = 0; hf < 2; hf++)
                redL[wn * 64 + wm * 32 + mt * 16 + g + hf * 8] = srow[mt][hf];
    }
    __syncthreads();
    if (wn == 0 && t == 0) {
        #pragma unroll
        for (int mt = 0; mt < 2; mt++)
            #pragma unroll
            for (int hf = 0; hf < 2; hf++) {
                int row = wm * 32 + mt * 16 + g + hf * 8;
                size_t ri = (size_t)(bh * NT + q0 + row) * NKT + blockIdx.x;
                gPartM[ri] = mrow[mt][hf];
                gPartL[ri] = redL[row] + redL[64 + row] + redL[128 + row] + redL[192 + row];
            }
    }

    // ---- store SPLIT exp values ----
    #pragma unroll
    for (int mt = 0; mt < 2; mt++)
        #pragma unroll
        for (int nt = 0; nt < 4; nt++) {
            int kb = wn * 32 + nt * 8 + t * 2;
            int row0 = wm * 32 + mt * 16 + g;
            unsigned h0, l0;
            cvt_pair2(accK[mt][nt][0], accK[mt][nt][1], h0, l0);
            size_t w0 = (size_t)(bh * NT + q0 + row0) * 512 + ((k0 + kb) >> 1);
            gSh[w0] = h0; gSl[w0] = l0;
            cvt_pair2(accK[mt][nt][2], accK[mt][nt][3], h0, l0);
            size_t w1 = (size_t)(bh * NT + q0 + row0 + 8) * 512 + ((k0 + kb) >> 1);
            gSh[w1] = h0; gSl[w1] = l0;
        }
}

// ---------------- O = P @ V: cp.async double-buffer, inline scales --------
#define PV_BUFW ((4 * 64) * PW)

__device__ __forceinline__ void pv_issue(int bh, int q0, int tid, unsigned uS,
                                         int c, int bi) {
    int kk0w = c * 32;
    unsigned pH = uS + bi * PV_BUFW * 4;
    unsigned pL = pH + 64 * PW * 4;
    unsigned vH = pL + 64 * PW * 4;
    unsigned vL = vH + 64 * PW * 4;
    #pragma unroll
    for (int i = 0; i < 4; i++) {
        int idx = tid + i * 128;
        int row = idx >> 3, w4 = (idx & 7) << 2;
        size_t pb = (size_t)(bh * NT + q0 + row) * 512 + kk0w + w4;
        cpa16(pH + (row * PW + w4) * 4, &gSh[pb]);
        cpa16(pL + (row * PW + w4) * 4, &gSl[pb]);
    }
    #pragma unroll
    for (int i = 0; i < 4; i++) {
        int idx = tid + i * 128;
        int row = idx >> 3, w4 = (idx & 7) << 2;
        size_t vb = (size_t)(bh * 64 + row) * 512 + kk0w + w4;
        cpa16(vH + (row * PW + w4) * 4, &gVth[vb]);
        cpa16(vL + (row * PW + w4) * 4, &gVtl[vb]);
    }
    cpa_commit();
}

__global__ void pv_tc() {
    extern __shared__ unsigned sm[];
    float* Ss = (float*)(sm + 2 * PV_BUFW);   // [64 rows][NKT] scales
    int tid = threadIdx.x;
    int warp = tid >> 5, lane = tid & 31;
    int wm = warp >> 1, wn = warp & 1;
    int g = lane >> 2, t = lane & 3;
    int bh = blockIdx.y, b = bh >> 3;
    int q0 = blockIdx.x * 64;
    float acc[2][4][4] = {};
    unsigned uS = smaddr(sm);
    unsigned aoff = AOFF(lane), boff = BOFF(lane);

    pv_issue(bh, q0, tid, uS, 0, 0);

    // inline per-row softmax scales (replaces reduce_kernel)
    if (tid < 64) {
        size_t base = (size_t)(bh * NT + q0 + tid) * NKT;
        float pm[NKT], pl[NKT];
        float m = -1e30f;
        #pragma unroll
        for (int i = 0; i < NKT; i++) {
            pm[i] = gPartM[base + i];
            pl[i] = gPartL[base + i];
            m = fmaxf(m, pm[i]);
        }
        float l = 0.f;
        #pragma unroll
        for (int i = 0; i < NKT; i++) l += __expf(pm[i] - m) * pl[i];
        float inv = 1.f / l;
        #pragma unroll
        for (int i = 0; i < NKT; i++) Ss[tid * NKT + i] = __expf(pm[i] - m) * inv;
    }

    for (int c = 0; c < 16; c++) {
        int bi = c & 1;
        int kt = c >> 1;   // NKT tile index: 2 chunks (64 pos each) per 128-pos tile
        if (c < 15) {
            pv_issue(bh, q0, tid, uS, c + 1, bi ^ 1);
            cpa_wait1();
        } else {
            cpa_wait0();
        }
        __syncthreads();
        unsigned uPh = uS + bi * PV_BUFW * 4;
        unsigned uPl = uPh + 64 * PW * 4;
        unsigned uVh = uPl + 64 * PW * 4;
        unsigned uVl = uVh + 64 * PW * 4;
        float ta[2][4][4] = {};
        #pragma unroll
        for (int kw = 0; kw < 32; kw += 8) {
            unsigned ah[2][4], al[2][4];
            #pragma unroll
            for (int mt = 0; mt < 2; mt++) {
                unsigned base = (((wm * 32 + mt * 16) * PW + kw) << 2) + aoff;
                ldsm4(ah[mt][0], ah[mt][1], ah[mt][2], ah[mt][3], uPh + base);
                ldsm4(al[mt][0], al[mt][1], al[mt][2], al[mt][3], uPl + base);
            }
            #pragma unroll
            for (int pair = 0; pair < 2; pair++) {
                unsigned base = (((wn * 32 + pair * 16) * PW + kw) << 2) + boff;
                unsigned bhv[4], blv[4];
                ldsm4(bhv[0], bhv[1], bhv[2], bhv[3], uVh + base);
                ldsm4(blv[0], blv[1], blv[2], blv[3], uVl + base);
                #pragma unroll
                for (int half = 0; half < 2; half++) {
                    int nt = pair * 2 + half;
                    #pragma unroll
                    for (int mt = 0; mt < 2; mt++) {
                        mma16(ta[mt][nt], ah[mt][0], ah[mt][1], ah[mt][2], ah[mt][3],
                              bhv[half*2], bhv[half*2+1]);
                        mma16(ta[mt][nt], ah[mt][0], ah[mt][1], ah[mt][2], ah[mt][3],
                              blv[half*2], blv[half*2+1]);
                        mma16(ta[mt][nt], al[mt][0], al[mt][1], al[mt][2], al[mt][3],
                              bhv[half*2], bhv[half*2+1]);
                    }
                }
            }
        }
        __syncthreads();
        float s0[2], s1[2];
        #pragma unroll
        for (int mt = 0; mt < 2; mt++) {
            s0[mt] = Ss[(wm * 32 + mt * 16 + g) * NKT + kt];
            s1[mt] = Ss[(wm * 32 + mt * 16 + g + 8) * NKT + kt];
        }
        #pragma unroll
        for (int mt = 0; mt < 2; mt++)
            #pragma unroll
            for (int nt = 0; nt < 4; nt++) {
                acc[mt][nt][0] += s0[mt] * ta[mt][nt][0];
                acc[mt][nt][1] += s0[mt] * ta[mt][nt][1];
                acc[mt][nt][2] += s1[mt] * ta[mt][nt][2];
                acc[mt][nt][3] += s1[mt] * ta[mt][nt][3];
            }
    }
    int h = bh & 7;
    #pragma unroll
    for (int mt = 0; mt < 2; mt++)
        #pragma unroll
        for (int nt = 0; nt < 4; nt++) {
            int row = q0 + wm * 32 + mt * 16 + g;
            int col = wn * 32 + nt * 8 + t * 2;
            unsigned hv, lv;
            cvt_pair2(acc[mt][nt][0], acc[mt][nt][1], hv, lv);
            size_t w0 = (size_t)(b * NT + row) * NW + h * 32 + (col >> 1);
            gOh[w0] = hv; gOl[w0] = lv;
            cvt_pair2(acc[mt][nt][2], acc[mt][nt][3], hv, lv);
            size_t w1 = (size_t)(b * NT + row + 8) * NW + h * 32 + (col >> 1);
            gOh[w1] = hv; gOl[w1] = lv;
        }
}

// -------------------------------------------------------------------------
extern "C" void kernel_launch(void* const* d_in, const int* in_sizes, int n_in,
                              void* d_out, int out_size) {
    const float* query = (const float*)d_in[0];
    const float* key_  = (const float*)d_in[1];
    const float* value = (const float*)d_in[2];
    const float* Wq = (const float*)d_in[3];
    const float* bq = (const float*)d_in[4];
    const float* Wk = (const float*)d_in[5];
    const float* bk = (const float*)d_in[6];
    const float* Wv = (const float*)d_in[7];
    const float* bv = (const float*)d_in[8];
    const float* Wp = (const float*)d_in[9];
    const float* bp = (const float*)d_in[10];
    const float* Wo = (const float*)d_in[11];
    const float* bo = (const float*)d_in[12];
    const float* ub = (const float*)d_in[13];
    const float* vb = (const float*)d_in[14];
    float* out = (float*)d_out;

    unsigned *pAh, *pAl, *pWh, *pWl, *pPEh, *pPEl;
    unsigned *pQh, *pQl, *pKh, *pKl, *pEh, *pEl, *pOh, *pOl;
    float *pV;
    cudaGetSymbolAddress((void**)&pAh, gAh);
    cudaGetSymbolAddress((void**)&pAl, gAl);
    cudaGetSymbolAddress((void**)&pWh, gWh);
    cudaGetSymbolAddress((void**)&pWl, gWl);
    cudaGetSymbolAddress((void**)&pPEh, gPEh);
    cudaGetSymbolAddress((void**)&pPEl, gPEl);
    cudaGetSymbolAddress((void**)&pQh, gQh);
    cudaGetSymbolAddress((void**)&pQl, gQl);
    cudaGetSymbolAddress((void**)&pKh, gKh);
    cudaGetSymbolAddress((void**)&pKl, gKl);
    cudaGetSymbolAddress((void**)&pEh, gEh);
    cudaGetSymbolAddress((void**)&pEl, gEl);
    cudaGetSymbolAddress((void**)&pOh, gOh);
    cudaGetSymbolAddress((void**)&pOl, gOl);
    cudaGetSymbolAddress((void**)&pV, gV);

    const int PROJ_SMEM   = 2 * PROJ_BUFW * 4;                                // 110592
    const int SCORES_SMEM = (2 * PW * (64 + 128 + 128 + 64) + 512) * 4;       // 112640
    const int PV_SMEM     = 2 * PV_BUFW * 4 + 64 * NKT * 4;                   // 75776
    cudaFuncSetAttribute(proj_all,  cudaFuncAttributeMaxDynamicSharedMemorySize, PROJ_SMEM);
    cudaFuncSetAttribute(proj_out,  cudaFuncAttributeMaxDynamicSharedMemorySize, PROJ_SMEM);
    cudaFuncSetAttribute(scores_tc, cudaFuncAttributeMaxDynamicSharedMemorySize, SCORES_SMEM);
    cudaFuncSetAttribute(pv_tc,     cudaFuncAttributeMaxDynamicSharedMemorySize, PV_SMEM);

    ProjArgs pa;
    pa.Ah[0] = pAh;          pa.Al[0] = pAl;          pa.Wh[0] = pWh;          pa.Wl[0] = pWl;
    pa.bias[0] = bq; pa.Ch[0] = pQh; pa.Cl[0] = pQl; pa.Cf[0] = 0; pa.M[0] = NM; pa.split[0] = 1;
    pa.Ah[1] = pAh + AW;     pa.Al[1] = pAl + AW;     pa.Wh[1] = pWh + WW;     pa.Wl[1] = pWl + WW;
    pa.bias[1] = bk; pa.Ch[1] = pKh; pa.Cl[1] = pKl; pa.Cf[1] = 0; pa.M[1] = NM; pa.split[1] = 1;
    pa.Ah[2] = pAh + 2 * AW; pa.Al[2] = pAl + 2 * AW; pa.Wh[2] = pWh + 2 * WW; pa.Wl[2] = pWl + 2 * WW;
    pa.bias[2] = bv; pa.Ch[2] = 0; pa.Cl[2] = 0; pa.Cf[2] = pV; pa.M[2] = NM; pa.split[2] = 0;
    pa.Ah[3] = pPEh;         pa.Al[3] = pPEl;         pa.Wh[3] = pWh + 3 * WW; pa.Wl[3] = pWl + 3 * WW;
    pa.bias[3] = bp; pa.Ch[3] = pEh; pa.Cl[3] = pEl; pa.Cf[3] = 0; pa.M[3] = NR; pa.split[3] = 1;

    pe_presplit<<<(NR * 256 + 3 * AW + 5 * WW + 255) / 256, 256>>>(
        query, key_, value, Wq, Wk, Wv, Wp, Wo);
    proj_all<<<896, 256, PROJ_SMEM>>>(pa);
    vtukve<<<512 + 6143, 256>>>(ub, vb);
    scores_tc<<<dim3(8, 16, 32), 256, SCORES_SMEM>>>();
    pv_tc<<<dim3(16, 32), 128, PV_SMEM>>>();
    proj_out<<<dim3(8, 32), 256, PROJ_SMEM>>>(pOh, pOl, pWh + 4 * WW, pWl + 4 * WW, bo, out, NM);
}